// round 13
// baseline (speedup 1.0000x reference)
#include <cuda_runtime.h>
#include <math.h>

// Problem constants
#define BB 4
#define LS 1024
#define DMOD 1024
#define NH 16
#define DKH 64
#define DVH 64
#define ZH (BB * NH)

#define OUT_ELEMS ((long long)BB * LS * DMOD)            // 4194304
#define ATT_ELEMS ((long long)ZH * LS * LS)              // 67108864

// -------------------- scratch (device globals; no allocation allowed) ------
__device__ float g_qh[ZH * LS * DKH];        // [B,H,L,DK]
__device__ float g_kh[ZH * LS * DKH];
__device__ float g_vh[ZH * LS * DVH];
__device__ float g_ctx[BB * LS * NH * DVH];  // [B,L,H*DV]
__device__ float g_fc[BB * LS * DMOD];       // pre-LN fc output
__device__ float g_part[(size_t)ZH * LS * 16]; // per-(z,row) partial exp sums
__device__ float g_invsum[ZH * LS];          // 1 / rowsum
__device__ float g_attn[(size_t)ZH * LS * LS]; // attn scratch (fallback dest)
__device__ float g_outs[BB * LS * DMOD];     // fallback out sink

// ---------------------------------------------------------------------------
// helpers
// ---------------------------------------------------------------------------
__device__ __forceinline__ unsigned f2tf(float f) {
    unsigned r;
    asm("cvt.rna.tf32.f32 %0, %1;" : "=r"(r) : "f"(f));
    return r;
}

__device__ __forceinline__ void mma8(float& c0, float& c1, float& c2, float& c3,
                                     unsigned a0, unsigned a1, unsigned a2, unsigned a3,
                                     unsigned b0, unsigned b1) {
    asm volatile(
        "mma.sync.aligned.m16n8k8.row.col.f32.tf32.tf32.f32 "
        "{%0,%1,%2,%3}, {%4,%5,%6,%7}, {%8,%9}, {%0,%1,%2,%3};\n"
        : "+f"(c0), "+f"(c1), "+f"(c2), "+f"(c3)
        : "r"(a0), "r"(a1), "r"(a2), "r"(a3), "r"(b0), "r"(b1));
}

__device__ __forceinline__ void cpa16(void* s, const void* g) {
    asm volatile("cp.async.cg.shared.global [%0], [%1], 16;\n"
        :: "r"((unsigned)__cvta_generic_to_shared(s)), "l"(g) : "memory");
}
__device__ __forceinline__ void cpa_commit() {
    asm volatile("cp.async.commit_group;\n" ::: "memory");
}
template <int N> __device__ __forceinline__ void cpa_wait() {
    asm volatile("cp.async.wait_group %0;\n" :: "n"(N) : "memory");
}

// ---------------------------------------------------------------------------
// TF32 NT GEMM + bias, cp.async double-buffered, 3 CTAs/SM.
// Tile 128(m) x 64(n), BK=32, 256 threads (8 warps, 4m x 2n, warp 32x32).
// ---------------------------------------------------------------------------
#define GEMM_SMEM_BYTES ((2 * 128 * 36 + 2 * 64 * 36) * 4)

__device__ __forceinline__ void gemm_body(
    const float* __restrict__ A, const float* __restrict__ W,
    const float* __restrict__ bias, float* __restrict__ out,
    int K, int N, int Dhead, float* gsm)
{
    float* As = gsm;
    float* Ws = gsm + 2 * 128 * 36;

    const int t = threadIdx.x, lane = t & 31, w = t >> 5;
    const int wm = w >> 1, wn = w & 1;
    const int g = lane >> 2, tg = lane & 3;
    const int rowBase = blockIdx.y * 128;
    const int colBase = blockIdx.x * 64;

    const float* Ab = A + (size_t)rowBase * K;
    const float* Wb = W + (size_t)colBase * K;

    float c[2][4][4];
#pragma unroll
    for (int mt = 0; mt < 2; mt++)
#pragma unroll
        for (int nt = 0; nt < 4; nt++)
#pragma unroll
            for (int i = 0; i < 4; i++) c[mt][nt][i] = 0.f;

    const int nk = K >> 5;

    {
#pragma unroll
        for (int i = 0; i < 4; i++) {
            const int idx4 = t + 256 * i;
            const int row = idx4 >> 3, c4 = (idx4 & 7) * 4;
            cpa16(&As[row * 36 + c4], Ab + (size_t)row * K + c4);
        }
#pragma unroll
        for (int i = 0; i < 2; i++) {
            const int idx4 = t + 256 * i;
            const int row = idx4 >> 3, c4 = (idx4 & 7) * 4;
            cpa16(&Ws[row * 36 + c4], Wb + (size_t)row * K + c4);
        }
        cpa_commit();
    }

    for (int kt = 0; kt < nk; kt++) {
        if (kt + 1 < nk) {
            float* Ad = As + ((kt + 1) & 1) * (128 * 36);
            float* Wd = Ws + ((kt + 1) & 1) * (64 * 36);
            const int ko = (kt + 1) * 32;
#pragma unroll
            for (int i = 0; i < 4; i++) {
                const int idx4 = t + 256 * i;
                const int row = idx4 >> 3, c4 = (idx4 & 7) * 4;
                cpa16(&Ad[row * 36 + c4], Ab + (size_t)row * K + ko + c4);
            }
#pragma unroll
            for (int i = 0; i < 2; i++) {
                const int idx4 = t + 256 * i;
                const int row = idx4 >> 3, c4 = (idx4 & 7) * 4;
                cpa16(&Wd[row * 36 + c4], Wb + (size_t)row * K + ko + c4);
            }
            cpa_commit();
            cpa_wait<1>();
        } else {
            cpa_wait<0>();
        }
        __syncthreads();

        const float* Ac = As + (kt & 1) * (128 * 36);
        const float* Wc = Ws + (kt & 1) * (64 * 36);
#pragma unroll
        for (int ks = 0; ks < 4; ks++) {
            const int kk = ks * 8;
            unsigned a[2][4], bf[4][2];
#pragma unroll
            for (int mt = 0; mt < 2; mt++) {
                const int r = (wm * 32 + mt * 16 + g) * 36 + kk + tg;
                a[mt][0] = f2tf(Ac[r]);
                a[mt][1] = f2tf(Ac[r + 8 * 36]);
                a[mt][2] = f2tf(Ac[r + 4]);
                a[mt][3] = f2tf(Ac[r + 8 * 36 + 4]);
            }
#pragma unroll
            for (int nt = 0; nt < 4; nt++) {
                const int r = (wn * 32 + nt * 8 + g) * 36 + kk + tg;
                bf[nt][0] = f2tf(Wc[r]);
                bf[nt][1] = f2tf(Wc[r + 4]);
            }
#pragma unroll
            for (int mt = 0; mt < 2; mt++)
#pragma unroll
                for (int nt = 0; nt < 4; nt++)
                    mma8(c[mt][nt][0], c[mt][nt][1], c[mt][nt][2], c[mt][nt][3],
                         a[mt][0], a[mt][1], a[mt][2], a[mt][3],
                         bf[nt][0], bf[nt][1]);
        }
        __syncthreads();
    }

    const int H = N / Dhead;
#pragma unroll
    for (int mt = 0; mt < 2; mt++) {
        const int rr = rowBase + wm * 32 + mt * 16 + g;
        const int b_ = rr >> 10, l = rr & 1023;
#pragma unroll
        for (int nt = 0; nt < 4; nt++) {
            const int cc = colBase + wn * 32 + nt * 8 + 2 * tg;
            const int h = cc / Dhead, d = cc % Dhead;
            const size_t dst = (((size_t)(b_ * H + h)) * LS + l) * Dhead + d;
            const float b0 = bias[cc], b1 = bias[cc + 1];
            *(float2*)&out[dst]             = make_float2(c[mt][nt][0] + b0, c[mt][nt][1] + b1);
            *(float2*)&out[dst + 8 * Dhead] = make_float2(c[mt][nt][2] + b0, c[mt][nt][3] + b1);
        }
    }
}

__global__ void __launch_bounds__(256, 3)
gemm_v2(const float* __restrict__ A, const float* __restrict__ W,
        const float* __restrict__ bias, float* __restrict__ out,
        int K, int N, int Dhead)
{
    extern __shared__ float gsm[];
    gemm_body(A, W, bias, out, K, N, Dhead, gsm);
}

__global__ void __launch_bounds__(256, 3)
gemm_qkv(const float* __restrict__ q, const float* __restrict__ k,
         const float* __restrict__ v,
         const float* __restrict__ w_q, const float* __restrict__ w_k,
         const float* __restrict__ w_v,
         const float* __restrict__ b_q, const float* __restrict__ b_k,
         const float* __restrict__ b_v,
         float* __restrict__ oq, float* __restrict__ ok, float* __restrict__ ov)
{
    extern __shared__ float gsm[];
    const int zz = blockIdx.z;
    const float* A  = (zz == 0) ? q   : (zz == 1) ? k   : v;
    const float* W  = (zz == 0) ? w_q : (zz == 1) ? w_k : w_v;
    const float* bi = (zz == 0) ? b_q : (zz == 1) ? b_k : b_v;
    float*       o  = (zz == 0) ? oq  : (zz == 1) ? ok  : ov;
    gemm_body(A, W, bi, o, DMOD, NH * DKH, DKH, gsm);
}

// ---------------------------------------------------------------------------
// Scores v5 + streaming hints: __ldcs gate, __stcs attn.
// ---------------------------------------------------------------------------
#define SC_SMEM_BYTES (2 * 64 * 68 * 4)

__global__ void __launch_bounds__(256, 4)
scores_v5(const float* __restrict__ qh, const float* __restrict__ kh,
          const float* __restrict__ gate, const int* __restrict__ mask,
          float* __restrict__ attn, float* __restrict__ part)
{
    extern __shared__ float ssm[];
    float* Qs  = ssm;                  // 64 x 68 (later aliased as Ss)
    float* Ksm = ssm + 64 * 68;        // 64 x 68 (later aliased as redsh)

    const int t = threadIdx.x, lane = t & 31, w = t >> 5;
    const int wm = w >> 2, wn = w & 3;     // 2m x 4n warps, warp tile 32x16
    const int g = lane >> 2, tg = lane & 3;
    const int z = blockIdx.z, b = z >> 4;
    const int qBase = blockIdx.y * 64;
    const int kBase = blockIdx.x * 64;

    const float* Q  = qh + (size_t)z * (LS * DKH) + qBase * DKH;
    const float* Kp = kh + (size_t)z * (LS * DKH) + kBase * DKH;

    {
        const int row = t >> 4, c = (t & 15) * 4;
        const int so = row * 68 + c;
        const int go = row * DKH + c;
#pragma unroll
        for (int i = 0; i < 4; i++) {
            cpa16(&Qs[so + i * 16 * 68], Q + go + i * 16 * DKH);
            cpa16(&Ksm[so + i * 16 * 68], Kp + go + i * 16 * DKH);
        }
    }
    cpa_commit();
    cpa_wait<0>();
    __syncthreads();

    float s[2][2][4];
#pragma unroll
    for (int mt = 0; mt < 2; mt++)
#pragma unroll
        for (int nt = 0; nt < 2; nt++)
#pragma unroll
            for (int i = 0; i < 4; i++) s[mt][nt][i] = 0.f;

    const int abase = (wm * 32 + g) * 68 + tg;
    const int bbase = (wn * 16 + g) * 68 + tg;
#pragma unroll
    for (int ks = 0; ks < 8; ks++) {
        const int kk = ks * 8;
        unsigned a[2][4], bf[2][2];
#pragma unroll
        for (int mt = 0; mt < 2; mt++) {
            const int r = abase + mt * (16 * 68) + kk;
            a[mt][0] = f2tf(Qs[r]);
            a[mt][1] = f2tf(Qs[r + 8 * 68]);
            a[mt][2] = f2tf(Qs[r + 4]);
            a[mt][3] = f2tf(Qs[r + 8 * 68 + 4]);
        }
#pragma unroll
        for (int nt = 0; nt < 2; nt++) {
            const int r = bbase + nt * (8 * 68) + kk;
            bf[nt][0] = f2tf(Ksm[r]);
            bf[nt][1] = f2tf(Ksm[r + 4]);
        }
#pragma unroll
        for (int mt = 0; mt < 2; mt++)
#pragma unroll
            for (int nt = 0; nt < 2; nt++)
                mma8(s[mt][nt][0], s[mt][nt][1], s[mt][nt][2], s[mt][nt][3],
                     a[mt][0], a[mt][1], a[mt][2], a[mt][3],
                     bf[nt][0], bf[nt][1]);
    }

    __syncthreads();   // Q/K smem reads done; safe to alias

    float* Ss = Qs;
    {
        const int rb = wm * 32 + g;
        const int cb = wn * 16 + 2 * tg;
#pragma unroll
        for (int mt = 0; mt < 2; mt++) {
            const int ro = (rb + mt * 16) * 68;
#pragma unroll
            for (int nt = 0; nt < 2; nt++) {
                const int col = cb + nt * 8;
                *(float2*)&Ss[ro + col]          = make_float2(s[mt][nt][0], s[mt][nt][1]);
                *(float2*)&Ss[ro + 8 * 68 + col] = make_float2(s[mt][nt][2], s[mt][nt][3]);
            }
        }
    }
    __syncthreads();

    float* redsh = Ksm;
    {
        const int row0 = t >> 4, c4 = (t & 15) * 4;
        const size_t rowcol = (size_t)(qBase + row0) * LS + kBase + c4;
        const float* gp = gate + (size_t)z * (LS * LS) + rowcol;
        const int*   mp = mask + (size_t)b * (LS * LS) + rowcol;
        float*       ap = attn + (size_t)z * (LS * LS) + rowcol;
        int so = row0 * 68 + c4;
#pragma unroll
        for (int i = 0; i < 4; i++) {
            float4 sv = *(float4*)&Ss[so];
            float4 gv = __ldcs((const float4*)gp);   // streaming: no reuse
            int4   mv = *(const int4*)mp;            // mask reused across heads
            float4 ev;
            ev.x = (mv.x > 0) ? 0.f : __expf(sv.x * 0.125f * gv.x);
            ev.y = (mv.y > 0) ? 0.f : __expf(sv.y * 0.125f * gv.y);
            ev.z = (mv.z > 0) ? 0.f : __expf(sv.z * 0.125f * gv.z);
            ev.w = (mv.w > 0) ? 0.f : __expf(sv.w * 0.125f * gv.w);
            __stcs((float4*)ap, ev);                 // streaming store
            float sum = (ev.x + ev.y) + (ev.z + ev.w);
            sum += __shfl_xor_sync(0xffffffffu, sum, 1);
            sum += __shfl_xor_sync(0xffffffffu, sum, 2);
            sum += __shfl_xor_sync(0xffffffffu, sum, 4);
            sum += __shfl_xor_sync(0xffffffffu, sum, 8);
            if ((lane & 15) == 0) redsh[row0 + 16 * i] = sum;
            so += 16 * 68;
            gp += 16 * LS; mp += 16 * LS; ap += 16 * LS;
        }
    }
    __syncthreads();
    if (t < 64)
        part[((size_t)z * LS + qBase + t) * 16 + blockIdx.x] = redsh[t];
}

// ---------------------------------------------------------------------------
// Reduce 16 partials -> 1/rowsum.  grid 256, block 256.
// ---------------------------------------------------------------------------
__global__ void reduce_inv(const float* __restrict__ part, float* __restrict__ invsum)
{
    const int i = blockIdx.x * 256 + threadIdx.x;   // 65536 rows
    float s = 0.f;
#pragma unroll
    for (int j = 0; j < 16; j++) s += part[(size_t)i * 16 + j];
    invsum[i] = 1.f / s;
}

// ---------------------------------------------------------------------------
// AV v5: q-tile 32 -> smem 54.3 KB -> 4 CTAs/SM, halved accumulators.
// P+V cp.async double-buffered, MMA on unnormalized P, ctx scaled at end,
// conditional __stcs attn write-back.
// 256 threads (8 warps, 2m x 4n, warp tile 16x16).  grid (32, 64).
// ---------------------------------------------------------------------------
#define AV_SMEM_BYTES ((2 * 32 * 68 + 2 * 64 * 72) * 4)

__global__ void __launch_bounds__(256, 4)
av_v5(float* __restrict__ attn, const float* __restrict__ invsum,
      const float* __restrict__ vh, float* __restrict__ ctx, int write_attn)
{
    extern __shared__ float avsm[];
    float* Ps = avsm;                   // 2 x (32 x 68)
    float* Vs = avsm + 2 * 32 * 68;     // 2 x (64 x 72)
    __shared__ float invsh[32];

    const int t = threadIdx.x, lane = t & 31, w = t >> 5;
    const int wm = w >> 2, wn = w & 3;     // 2m x 4n warps, warp tile 16x16
    const int g = lane >> 2, tg = lane & 3;
    const int z = blockIdx.y, b = z >> 4, h = z & 15;
    const int rowBase = blockIdx.x * 32;

    float* P = attn + (size_t)z * (LS * LS) + (size_t)rowBase * LS;
    const float* V = vh + (size_t)z * (LS * DVH);

    if (t < 32) invsh[t] = invsum[z * LS + rowBase + t];

    const int pr0 = t >> 4,           pc0 = (t & 15) * 4;
    const int pr1 = (t + 256) >> 4,   pc1 = pc0;
    int vr[4];
    const int vc = (t & 15) * 4;
#pragma unroll
    for (int i = 0; i < 4; i++) vr[i] = (t >> 4) + 16 * i;

    float c[2][4];
#pragma unroll
    for (int nt = 0; nt < 2; nt++)
#pragma unroll
        for (int i = 0; i < 4; i++) c[nt][i] = 0.f;

    cpa16(&Ps[pr0 * 68 + pc0], P + (size_t)pr0 * LS + pc0);
    cpa16(&Ps[pr1 * 68 + pc1], P + (size_t)pr1 * LS + pc1);
#pragma unroll
    for (int i = 0; i < 4; i++)
        cpa16(&Vs[vr[i] * 72 + vc], V + (size_t)vr[i] * DVH + vc);
    cpa_commit();

    for (int kt = 0; kt < 16; kt++) {
        const bool more = (kt + 1 < 16);
        if (more) {
            const int ko = (kt + 1) * 64;
            float* Pd = Ps + ((kt + 1) & 1) * (32 * 68);
            float* Vd = Vs + ((kt + 1) & 1) * (64 * 72);
            cpa16(&Pd[pr0 * 68 + pc0], P + (size_t)pr0 * LS + ko + pc0);
            cpa16(&Pd[pr1 * 68 + pc1], P + (size_t)pr1 * LS + ko + pc1);
#pragma unroll
            for (int i = 0; i < 4; i++)
                cpa16(&Vd[vr[i] * 72 + vc], V + (size_t)(ko + vr[i]) * DVH + vc);
            cpa_commit();
            cpa_wait<1>();
        } else {
            cpa_wait<0>();
        }
        __syncthreads();

        const float* Pc = Ps + (kt & 1) * (32 * 68);
        const float* Vc = Vs + (kt & 1) * (64 * 72);

        if (write_attn) {
            const int ko = kt * 64;
            float4 pv0 = *(const float4*)&Pc[pr0 * 68 + pc0];
            const float i0 = invsh[pr0];
            pv0.x *= i0; pv0.y *= i0; pv0.z *= i0; pv0.w *= i0;
            __stcs((float4*)(P + (size_t)pr0 * LS + ko + pc0), pv0);
            float4 pv1 = *(const float4*)&Pc[pr1 * 68 + pc1];
            const float i1 = invsh[pr1];
            pv1.x *= i1; pv1.y *= i1; pv1.z *= i1; pv1.w *= i1;
            __stcs((float4*)(P + (size_t)pr1 * LS + ko + pc1), pv1);
        }

#pragma unroll
        for (int ks = 0; ks < 8; ks++) {
            const int kk = ks * 8;
            const int r = (wm * 16 + g) * 68 + kk + tg;
            unsigned a0 = f2tf(Pc[r]);
            unsigned a1 = f2tf(Pc[r + 8 * 68]);
            unsigned a2 = f2tf(Pc[r + 4]);
            unsigned a3 = f2tf(Pc[r + 8 * 68 + 4]);
            unsigned bf[2][2];
#pragma unroll
            for (int nt = 0; nt < 2; nt++) {
                const int col = wn * 16 + nt * 8 + g;
                bf[nt][0] = f2tf(Vc[(kk + tg) * 72 + col]);
                bf[nt][1] = f2tf(Vc[(kk + tg + 4) * 72 + col]);
            }
#pragma unroll
            for (int nt = 0; nt < 2; nt++)
                mma8(c[nt][0], c[nt][1], c[nt][2], c[nt][3],
                     a0, a1, a2, a3, bf[nt][0], bf[nt][1]);
        }
        __syncthreads();
    }

    {
        const int lrow = wm * 16 + g;
        const int rr = rowBase + lrow;
        const float iv0 = invsh[lrow], iv1 = invsh[lrow + 8];
#pragma unroll
        for (int nt = 0; nt < 2; nt++) {
            const int d = wn * 16 + nt * 8 + 2 * tg;
            const size_t dst = ((size_t)(b * LS + rr)) * DMOD + h * 64 + d;
            *(float2*)&ctx[dst]            = make_float2(c[nt][0] * iv0, c[nt][1] * iv0);
            *(float2*)&ctx[dst + 8 * DMOD] = make_float2(c[nt][2] * iv1, c[nt][3] * iv1);
        }
    }
}

// ---------------------------------------------------------------------------
// Residual + LayerNorm with warp-shuffle reductions.  grid 4096, block 256.
// ---------------------------------------------------------------------------
__global__ void ln_kernel(const float* __restrict__ resid,
                          const float* __restrict__ gamma,
                          const float* __restrict__ beta,
                          const float* __restrict__ fcv,
                          float* __restrict__ out)
{
    __shared__ float wsum[8];
    const int r = blockIdx.x;
    const float* xf = fcv + (size_t)r * DMOD;
    const float* rz = resid + (size_t)r * DMOD;
    const int t = threadIdx.x, lane = t & 31, w = t >> 5;

    float v[4];
    float sum = 0.f;
#pragma unroll
    for (int j = 0; j < 4; j++) {
        v[j] = xf[t + 256 * j] + rz[t + 256 * j];
        sum += v[j];
    }
#pragma unroll
    for (int o = 16; o > 0; o >>= 1) sum += __shfl_xor_sync(0xffffffffu, sum, o);
    if (lane == 0) wsum[w] = sum;
    __syncthreads();
    float tot = wsum[0];
#pragma unroll
    for (int j = 1; j < 8; j++) tot += wsum[j];
    const float mu = tot * (1.f / DMOD);

    float vs = 0.f;
#pragma unroll
    for (int j = 0; j < 4; j++) {
        const float d = v[j] - mu;
        vs += d * d;
    }
#pragma unroll
    for (int o = 16; o > 0; o >>= 1) vs += __shfl_xor_sync(0xffffffffu, vs, o);
    __syncthreads();           // wsum reuse
    if (lane == 0) wsum[w] = vs;
    __syncthreads();
    float vtot = wsum[0];
#pragma unroll
    for (int j = 1; j < 8; j++) vtot += wsum[j];
    const float var = vtot * (1.f / DMOD);
    const float inv = rsqrtf(var + 1e-5f);
#pragma unroll
    for (int j = 0; j < 4; j++) {
        const int cc = t + 256 * j;
        out[(size_t)r * DMOD + cc] = (v[j] - mu) * inv * gamma[cc] + beta[cc];
    }
}

// ---------------------------------------------------------------------------
extern "C" void kernel_launch(void* const* d_in, const int* in_sizes, int n_in,
                              void* d_out, int out_size)
{
    const float* q    = (const float*)d_in[0];
    const float* k    = (const float*)d_in[1];
    const float* v    = (const float*)d_in[2];
    const int*   mask = (const int*)  d_in[3];
    const float* gate = (const float*)d_in[4];
    const float* w_q  = (const float*)d_in[5];
    const float* b_q  = (const float*)d_in[6];
    const float* w_k  = (const float*)d_in[7];
    const float* b_k  = (const float*)d_in[8];
    const float* w_v  = (const float*)d_in[9];
    const float* b_v  = (const float*)d_in[10];
    const float* w_fc = (const float*)d_in[11];
    const float* b_fc = (const float*)d_in[12];
    const float* ln_g = (const float*)d_in[13];
    const float* ln_b = (const float*)d_in[14];
    float* out = (float*)d_out;

    float *p_qh, *p_kh, *p_vh, *p_ctx, *p_fc, *p_part, *p_inv, *p_attn_s, *p_outs;
    cudaGetSymbolAddress((void**)&p_qh,     g_qh);
    cudaGetSymbolAddress((void**)&p_kh,     g_kh);
    cudaGetSymbolAddress((void**)&p_vh,     g_vh);
    cudaGetSymbolAddress((void**)&p_ctx,    g_ctx);
    cudaGetSymbolAddress((void**)&p_fc,     g_fc);
    cudaGetSymbolAddress((void**)&p_part,   g_part);
    cudaGetSymbolAddress((void**)&p_inv,    g_invsum);
    cudaGetSymbolAddress((void**)&p_attn_s, g_attn);
    cudaGetSymbolAddress((void**)&p_outs,   g_outs);

    // Reference returns (out, attn).  Resolve destinations from out_size.
    float* attn_ptr;
    float* out_ptr;
    const long long osz = (long long)out_size;
    if (osz >= OUT_ELEMS + ATT_ELEMS) {        // concatenated tuple
        out_ptr  = out;
        attn_ptr = out + OUT_ELEMS;
    } else if (osz >= ATT_ELEMS) {             // attn only
        out_ptr  = p_outs;
        attn_ptr = out;
    } else {                                   // out only
        out_ptr  = out;
        attn_ptr = p_attn_s;
    }
    const int write_attn = (attn_ptr != p_attn_s) ? 1 : 0;

    // opt in to >48KB dynamic smem (idempotent)
    cudaFuncSetAttribute(gemm_v2, cudaFuncAttributeMaxDynamicSharedMemorySize,
                         GEMM_SMEM_BYTES);
    cudaFuncSetAttribute(gemm_qkv, cudaFuncAttributeMaxDynamicSharedMemorySize,
                         GEMM_SMEM_BYTES);
    cudaFuncSetAttribute(av_v5, cudaFuncAttributeMaxDynamicSharedMemorySize,
                         AV_SMEM_BYTES);

    // 1) QKV projections (merged: one launch, grid.z selects q/k/v)
    gemm_qkv<<<dim3(16, 32, 3), 256, GEMM_SMEM_BYTES>>>(
        q, k, v, w_q, w_k, w_v, b_q, b_k, b_v, p_qh, p_kh, p_vh);

    // 2) Scores + gate/mask + exp + partial row sums (unnormalized attn)
    scores_v5<<<dim3(16, 16, ZH), 256, SC_SMEM_BYTES>>>(p_qh, p_kh, gate, mask, attn_ptr, p_part);

    // 3) partials -> 1/rowsum
    reduce_inv<<<256, 256>>>(p_part, p_inv);

    // 4) AV: MMA unnormalized P, scale ctx; conditional normalized attn write
    av_v5<<<dim3(32, ZH), 256, AV_SMEM_BYTES>>>(attn_ptr, p_inv, p_vh, p_ctx, write_attn);

    // 5) FC projection
    gemm_v2<<<dim3(16, 32), 256, GEMM_SMEM_BYTES>>>(p_ctx, w_fc, b_fc, p_fc, DMOD, DMOD, DMOD);

    // 6) Residual + LayerNorm -> final out
    ln_kernel<<<4096, 256>>>(q, ln_g, ln_b, p_fc, out_ptr);
}

// round 14
// speedup vs baseline: 1.0287x; 1.0287x over previous
#include <cuda_runtime.h>
#include <math.h>

// Problem constants
#define BB 4
#define LS 1024
#define DMOD 1024
#define NH 16
#define DKH 64
#define DVH 64
#define ZH (BB * NH)

#define OUT_ELEMS ((long long)BB * LS * DMOD)            // 4194304
#define ATT_ELEMS ((long long)ZH * LS * LS)              // 67108864

// -------------------- scratch (device globals; no allocation allowed) ------
__device__ float g_qh[ZH * LS * DKH];        // [B,H,L,DK]
__device__ float g_kh[ZH * LS * DKH];
__device__ float g_vh[ZH * LS * DVH];
__device__ float g_ctx[BB * LS * NH * DVH];  // [B,L,H*DV]
__device__ float g_fc[BB * LS * DMOD];       // pre-LN fc output
__device__ float g_part[(size_t)ZH * LS * 16]; // per-(z,row) partial exp sums
__device__ float g_invsum[ZH * LS];          // 1 / rowsum
__device__ float g_attn[(size_t)ZH * LS * LS]; // attn scratch (fallback dest)
__device__ float g_outs[BB * LS * DMOD];     // fallback out sink

// ---------------------------------------------------------------------------
// helpers
// ---------------------------------------------------------------------------
__device__ __forceinline__ unsigned f2tf(float f) {
    unsigned r;
    asm("cvt.rna.tf32.f32 %0, %1;" : "=r"(r) : "f"(f));
    return r;
}

__device__ __forceinline__ void mma8(float& c0, float& c1, float& c2, float& c3,
                                     unsigned a0, unsigned a1, unsigned a2, unsigned a3,
                                     unsigned b0, unsigned b1) {
    asm volatile(
        "mma.sync.aligned.m16n8k8.row.col.f32.tf32.tf32.f32 "
        "{%0,%1,%2,%3}, {%4,%5,%6,%7}, {%8,%9}, {%0,%1,%2,%3};\n"
        : "+f"(c0), "+f"(c1), "+f"(c2), "+f"(c3)
        : "r"(a0), "r"(a1), "r"(a2), "r"(a3), "r"(b0), "r"(b1));
}

__device__ __forceinline__ void cpa16(void* s, const void* g) {
    asm volatile("cp.async.cg.shared.global [%0], [%1], 16;\n"
        :: "r"((unsigned)__cvta_generic_to_shared(s)), "l"(g) : "memory");
}
__device__ __forceinline__ void cpa_commit() {
    asm volatile("cp.async.commit_group;\n" ::: "memory");
}
template <int N> __device__ __forceinline__ void cpa_wait() {
    asm volatile("cp.async.wait_group %0;\n" :: "n"(N) : "memory");
}

// ---------------------------------------------------------------------------
// TF32 NT GEMM + bias, cp.async double-buffered, 3 CTAs/SM (round 11 exact).
// Tile 128(m) x 64(n), BK=32, 256 threads (8 warps, 4m x 2n, warp 32x32).
// ---------------------------------------------------------------------------
#define GEMM_SMEM_BYTES ((2 * 128 * 36 + 2 * 64 * 36) * 4)

__device__ __forceinline__ void gemm_body(
    const float* __restrict__ A, const float* __restrict__ W,
    const float* __restrict__ bias, float* __restrict__ out,
    int K, int N, int Dhead, float* gsm)
{
    float* As = gsm;
    float* Ws = gsm + 2 * 128 * 36;

    const int t = threadIdx.x, lane = t & 31, w = t >> 5;
    const int wm = w >> 1, wn = w & 1;
    const int g = lane >> 2, tg = lane & 3;
    const int rowBase = blockIdx.y * 128;
    const int colBase = blockIdx.x * 64;

    const float* Ab = A + (size_t)rowBase * K;
    const float* Wb = W + (size_t)colBase * K;

    float c[2][4][4];
#pragma unroll
    for (int mt = 0; mt < 2; mt++)
#pragma unroll
        for (int nt = 0; nt < 4; nt++)
#pragma unroll
            for (int i = 0; i < 4; i++) c[mt][nt][i] = 0.f;

    const int nk = K >> 5;

    {
#pragma unroll
        for (int i = 0; i < 4; i++) {
            const int idx4 = t + 256 * i;
            const int row = idx4 >> 3, c4 = (idx4 & 7) * 4;
            cpa16(&As[row * 36 + c4], Ab + (size_t)row * K + c4);
        }
#pragma unroll
        for (int i = 0; i < 2; i++) {
            const int idx4 = t + 256 * i;
            const int row = idx4 >> 3, c4 = (idx4 & 7) * 4;
            cpa16(&Ws[row * 36 + c4], Wb + (size_t)row * K + c4);
        }
        cpa_commit();
    }

    for (int kt = 0; kt < nk; kt++) {
        if (kt + 1 < nk) {
            float* Ad = As + ((kt + 1) & 1) * (128 * 36);
            float* Wd = Ws + ((kt + 1) & 1) * (64 * 36);
            const int ko = (kt + 1) * 32;
#pragma unroll
            for (int i = 0; i < 4; i++) {
                const int idx4 = t + 256 * i;
                const int row = idx4 >> 3, c4 = (idx4 & 7) * 4;
                cpa16(&Ad[row * 36 + c4], Ab + (size_t)row * K + ko + c4);
            }
#pragma unroll
            for (int i = 0; i < 2; i++) {
                const int idx4 = t + 256 * i;
                const int row = idx4 >> 3, c4 = (idx4 & 7) * 4;
                cpa16(&Wd[row * 36 + c4], Wb + (size_t)row * K + ko + c4);
            }
            cpa_commit();
            cpa_wait<1>();
        } else {
            cpa_wait<0>();
        }
        __syncthreads();

        const float* Ac = As + (kt & 1) * (128 * 36);
        const float* Wc = Ws + (kt & 1) * (64 * 36);
#pragma unroll
        for (int ks = 0; ks < 4; ks++) {
            const int kk = ks * 8;
            unsigned a[2][4], bf[4][2];
#pragma unroll
            for (int mt = 0; mt < 2; mt++) {
                const int r = (wm * 32 + mt * 16 + g) * 36 + kk + tg;
                a[mt][0] = f2tf(Ac[r]);
                a[mt][1] = f2tf(Ac[r + 8 * 36]);
                a[mt][2] = f2tf(Ac[r + 4]);
                a[mt][3] = f2tf(Ac[r + 8 * 36 + 4]);
            }
#pragma unroll
            for (int nt = 0; nt < 4; nt++) {
                const int r = (wn * 32 + nt * 8 + g) * 36 + kk + tg;
                bf[nt][0] = f2tf(Wc[r]);
                bf[nt][1] = f2tf(Wc[r + 4]);
            }
#pragma unroll
            for (int mt = 0; mt < 2; mt++)
#pragma unroll
                for (int nt = 0; nt < 4; nt++)
                    mma8(c[mt][nt][0], c[mt][nt][1], c[mt][nt][2], c[mt][nt][3],
                         a[mt][0], a[mt][1], a[mt][2], a[mt][3],
                         bf[nt][0], bf[nt][1]);
        }
        __syncthreads();
    }

    const int H = N / Dhead;
#pragma unroll
    for (int mt = 0; mt < 2; mt++) {
        const int rr = rowBase + wm * 32 + mt * 16 + g;
        const int b_ = rr >> 10, l = rr & 1023;
#pragma unroll
        for (int nt = 0; nt < 4; nt++) {
            const int cc = colBase + wn * 32 + nt * 8 + 2 * tg;
            const int h = cc / Dhead, d = cc % Dhead;
            const size_t dst = (((size_t)(b_ * H + h)) * LS + l) * Dhead + d;
            const float b0 = bias[cc], b1 = bias[cc + 1];
            *(float2*)&out[dst]             = make_float2(c[mt][nt][0] + b0, c[mt][nt][1] + b1);
            *(float2*)&out[dst + 8 * Dhead] = make_float2(c[mt][nt][2] + b0, c[mt][nt][3] + b1);
        }
    }
}

__global__ void __launch_bounds__(256, 3)
gemm_v2(const float* __restrict__ A, const float* __restrict__ W,
        const float* __restrict__ bias, float* __restrict__ out,
        int K, int N, int Dhead)
{
    extern __shared__ float gsm[];
    gemm_body(A, W, bias, out, K, N, Dhead, gsm);
}

__global__ void __launch_bounds__(256, 3)
gemm_qkv(const float* __restrict__ q, const float* __restrict__ k,
         const float* __restrict__ v,
         const float* __restrict__ w_q, const float* __restrict__ w_k,
         const float* __restrict__ w_v,
         const float* __restrict__ b_q, const float* __restrict__ b_k,
         const float* __restrict__ b_v,
         float* __restrict__ oq, float* __restrict__ ok, float* __restrict__ ov)
{
    extern __shared__ float gsm[];
    const int zz = blockIdx.z;
    const float* A  = (zz == 0) ? q   : (zz == 1) ? k   : v;
    const float* W  = (zz == 0) ? w_q : (zz == 1) ? w_k : w_v;
    const float* bi = (zz == 0) ? b_q : (zz == 1) ? b_k : b_v;
    float*       o  = (zz == 0) ? oq  : (zz == 1) ? ok  : ov;
    gemm_body(A, W, bi, o, DMOD, NH * DKH, DKH, gsm);
}

// ---------------------------------------------------------------------------
// Scores v5 (round 11 structure): __ldcs ONLY on gate (single-use stream);
// attn written with normal stores (av re-reads it — keep it L2-resident).
// ---------------------------------------------------------------------------
#define SC_SMEM_BYTES (2 * 64 * 68 * 4)

__global__ void __launch_bounds__(256, 4)
scores_v5(const float* __restrict__ qh, const float* __restrict__ kh,
          const float* __restrict__ gate, const int* __restrict__ mask,
          float* __restrict__ attn, float* __restrict__ part)
{
    extern __shared__ float ssm[];
    float* Qs  = ssm;                  // 64 x 68 (later aliased as Ss)
    float* Ksm = ssm + 64 * 68;        // 64 x 68 (later aliased as redsh)

    const int t = threadIdx.x, lane = t & 31, w = t >> 5;
    const int wm = w >> 2, wn = w & 3;     // 2m x 4n warps, warp tile 32x16
    const int g = lane >> 2, tg = lane & 3;
    const int z = blockIdx.z, b = z >> 4;
    const int qBase = blockIdx.y * 64;
    const int kBase = blockIdx.x * 64;

    const float* Q  = qh + (size_t)z * (LS * DKH) + qBase * DKH;
    const float* Kp = kh + (size_t)z * (LS * DKH) + kBase * DKH;

    {
        const int row = t >> 4, c = (t & 15) * 4;
        const int so = row * 68 + c;
        const int go = row * DKH + c;
#pragma unroll
        for (int i = 0; i < 4; i++) {
            cpa16(&Qs[so + i * 16 * 68], Q + go + i * 16 * DKH);
            cpa16(&Ksm[so + i * 16 * 68], Kp + go + i * 16 * DKH);
        }
    }
    cpa_commit();
    cpa_wait<0>();
    __syncthreads();

    float s[2][2][4];
#pragma unroll
    for (int mt = 0; mt < 2; mt++)
#pragma unroll
        for (int nt = 0; nt < 2; nt++)
#pragma unroll
            for (int i = 0; i < 4; i++) s[mt][nt][i] = 0.f;

    const int abase = (wm * 32 + g) * 68 + tg;
    const int bbase = (wn * 16 + g) * 68 + tg;
#pragma unroll
    for (int ks = 0; ks < 8; ks++) {
        const int kk = ks * 8;
        unsigned a[2][4], bf[2][2];
#pragma unroll
        for (int mt = 0; mt < 2; mt++) {
            const int r = abase + mt * (16 * 68) + kk;
            a[mt][0] = f2tf(Qs[r]);
            a[mt][1] = f2tf(Qs[r + 8 * 68]);
            a[mt][2] = f2tf(Qs[r + 4]);
            a[mt][3] = f2tf(Qs[r + 8 * 68 + 4]);
        }
#pragma unroll
        for (int nt = 0; nt < 2; nt++) {
            const int r = bbase + nt * (8 * 68) + kk;
            bf[nt][0] = f2tf(Ksm[r]);
            bf[nt][1] = f2tf(Ksm[r + 4]);
        }
#pragma unroll
        for (int mt = 0; mt < 2; mt++)
#pragma unroll
            for (int nt = 0; nt < 2; nt++)
                mma8(s[mt][nt][0], s[mt][nt][1], s[mt][nt][2], s[mt][nt][3],
                     a[mt][0], a[mt][1], a[mt][2], a[mt][3],
                     bf[nt][0], bf[nt][1]);
    }

    __syncthreads();   // Q/K smem reads done; safe to alias

    float* Ss = Qs;
    {
        const int rb = wm * 32 + g;
        const int cb = wn * 16 + 2 * tg;
#pragma unroll
        for (int mt = 0; mt < 2; mt++) {
            const int ro = (rb + mt * 16) * 68;
#pragma unroll
            for (int nt = 0; nt < 2; nt++) {
                const int col = cb + nt * 8;
                *(float2*)&Ss[ro + col]          = make_float2(s[mt][nt][0], s[mt][nt][1]);
                *(float2*)&Ss[ro + 8 * 68 + col] = make_float2(s[mt][nt][2], s[mt][nt][3]);
            }
        }
    }
    __syncthreads();

    float* redsh = Ksm;
    {
        const int row0 = t >> 4, c4 = (t & 15) * 4;
        const size_t rowcol = (size_t)(qBase + row0) * LS + kBase + c4;
        const float* gp = gate + (size_t)z * (LS * LS) + rowcol;
        const int*   mp = mask + (size_t)b * (LS * LS) + rowcol;
        float*       ap = attn + (size_t)z * (LS * LS) + rowcol;
        int so = row0 * 68 + c4;
#pragma unroll
        for (int i = 0; i < 4; i++) {
            float4 sv = *(float4*)&Ss[so];
            float4 gv = __ldcs((const float4*)gp);   // gate: true single-use stream
            int4   mv = *(const int4*)mp;            // mask reused across 16 heads
            float4 ev;
            ev.x = (mv.x > 0) ? 0.f : __expf(sv.x * 0.125f * gv.x);
            ev.y = (mv.y > 0) ? 0.f : __expf(sv.y * 0.125f * gv.y);
            ev.z = (mv.z > 0) ? 0.f : __expf(sv.z * 0.125f * gv.z);
            ev.w = (mv.w > 0) ? 0.f : __expf(sv.w * 0.125f * gv.w);
            *(float4*)ap = ev;                       // normal store: av re-reads
            float sum = (ev.x + ev.y) + (ev.z + ev.w);
            sum += __shfl_xor_sync(0xffffffffu, sum, 1);
            sum += __shfl_xor_sync(0xffffffffu, sum, 2);
            sum += __shfl_xor_sync(0xffffffffu, sum, 4);
            sum += __shfl_xor_sync(0xffffffffu, sum, 8);
            if ((lane & 15) == 0) redsh[row0 + 16 * i] = sum;
            so += 16 * 68;
            gp += 16 * LS; mp += 16 * LS; ap += 16 * LS;
        }
    }
    __syncthreads();
    if (t < 64)
        part[((size_t)z * LS + qBase + t) * 16 + blockIdx.x] = redsh[t];
}

// ---------------------------------------------------------------------------
// Reduce 16 partials -> 1/rowsum.  grid 256, block 256.
// ---------------------------------------------------------------------------
__global__ void reduce_inv(const float* __restrict__ part, float* __restrict__ invsum)
{
    const int i = blockIdx.x * 256 + threadIdx.x;   // 65536 rows
    float s = 0.f;
#pragma unroll
    for (int j = 0; j < 16; j++) s += part[(size_t)i * 16 + j];
    invsum[i] = 1.f / s;
}

// ---------------------------------------------------------------------------
// AV v4 (round 11 exact): tile 64x64, BK=64, P+V cp.async double-buffered,
// MMA on unnormalized P, ctx scaled at end, conditional attn write-back.
// 3 CTAs/SM.
// ---------------------------------------------------------------------------
#define AV_SMEM_BYTES ((2 * 64 * 68 + 2 * 64 * 72) * 4)

__global__ void __launch_bounds__(256, 3)
av_v4(float* __restrict__ attn, const float* __restrict__ invsum,
      const float* __restrict__ vh, float* __restrict__ ctx, int write_attn)
{
    extern __shared__ float avsm[];
    float* Ps = avsm;                   // 2 x (64 x 68)
    float* Vs = avsm + 2 * 64 * 68;     // 2 x (64 x 72)
    __shared__ float invsh[64];

    const int t = threadIdx.x, lane = t & 31, w = t >> 5;
    const int wm = w >> 2, wn = w & 3;     // 2m x 4n warps, warp tile 32x16
    const int g = lane >> 2, tg = lane & 3;
    const int z = blockIdx.y, b = z >> 4, h = z & 15;
    const int rowBase = blockIdx.x * 64;

    float* P = attn + (size_t)z * LS * LS + (size_t)rowBase * LS;
    const float* V = vh + (size_t)z * LS * DVH;

    if (t < 64) invsh[t] = invsum[z * LS + rowBase + t];

    int lr[4], lc[4];
#pragma unroll
    for (int i = 0; i < 4; i++) {
        const int idx4 = t + 256 * i;
        lr[i] = idx4 >> 4;
        lc[i] = (idx4 & 15) * 4;
    }

    float c[2][2][4];
#pragma unroll
    for (int mt = 0; mt < 2; mt++)
#pragma unroll
        for (int nt = 0; nt < 2; nt++)
#pragma unroll
            for (int i = 0; i < 4; i++) c[mt][nt][i] = 0.f;

#pragma unroll
    for (int i = 0; i < 4; i++) {
        cpa16(&Ps[lr[i] * 68 + lc[i]], P + (size_t)lr[i] * LS + lc[i]);
        cpa16(&Vs[lr[i] * 72 + lc[i]], V + (size_t)lr[i] * DVH + lc[i]);
    }
    cpa_commit();

    for (int kt = 0; kt < 16; kt++) {
        const bool more = (kt + 1 < 16);
        if (more) {
            const int ko = (kt + 1) * 64;
            float* Pd = Ps + ((kt + 1) & 1) * (64 * 68);
            float* Vd = Vs + ((kt + 1) & 1) * (64 * 72);
#pragma unroll
            for (int i = 0; i < 4; i++) {
                cpa16(&Pd[lr[i] * 68 + lc[i]], P + (size_t)lr[i] * LS + ko + lc[i]);
                cpa16(&Vd[lr[i] * 72 + lc[i]], V + (size_t)(ko + lr[i]) * DVH + lc[i]);
            }
            cpa_commit();
            cpa_wait<1>();
        } else {
            cpa_wait<0>();
        }
        __syncthreads();

        const float* Pc = Ps + (kt & 1) * (64 * 68);
        const float* Vc = Vs + (kt & 1) * (64 * 72);

        if (write_attn) {
            const int ko = kt * 64;
#pragma unroll
            for (int i = 0; i < 4; i++) {
                float4 pv = *(const float4*)&Pc[lr[i] * 68 + lc[i]];
                const float iv = invsh[lr[i]];
                pv.x *= iv; pv.y *= iv; pv.z *= iv; pv.w *= iv;
                *(float4*)(P + (size_t)lr[i] * LS + ko + lc[i]) = pv;
            }
        }

#pragma unroll
        for (int ks = 0; ks < 8; ks++) {
            const int kk = ks * 8;
            unsigned a[2][4], bf[2][2];
#pragma unroll
            for (int mt = 0; mt < 2; mt++) {
                const int r = (wm * 32 + mt * 16 + g) * 68 + kk + tg;
                a[mt][0] = f2tf(Pc[r]);
                a[mt][1] = f2tf(Pc[r + 8 * 68]);
                a[mt][2] = f2tf(Pc[r + 4]);
                a[mt][3] = f2tf(Pc[r + 8 * 68 + 4]);
            }
#pragma unroll
            for (int nt = 0; nt < 2; nt++) {
                const int col = wn * 16 + nt * 8 + g;
                bf[nt][0] = f2tf(Vc[(kk + tg) * 72 + col]);
                bf[nt][1] = f2tf(Vc[(kk + tg + 4) * 72 + col]);
            }
#pragma unroll
            for (int mt = 0; mt < 2; mt++)
#pragma unroll
                for (int nt = 0; nt < 2; nt++)
                    mma8(c[mt][nt][0], c[mt][nt][1], c[mt][nt][2], c[mt][nt][3],
                         a[mt][0], a[mt][1], a[mt][2], a[mt][3],
                         bf[nt][0], bf[nt][1]);
        }
        __syncthreads();
    }

#pragma unroll
    for (int mt = 0; mt < 2; mt++) {
        const int lrow = wm * 32 + mt * 16 + g;
        const int rr = rowBase + lrow;
        const float iv0 = invsh[lrow], iv1 = invsh[lrow + 8];
#pragma unroll
        for (int nt = 0; nt < 2; nt++) {
            const int d = wn * 16 + nt * 8 + 2 * tg;
            const size_t dst = ((size_t)(b * LS + rr)) * DMOD + h * 64 + d;
            *(float2*)&ctx[dst]            = make_float2(c[mt][nt][0] * iv0, c[mt][nt][1] * iv0);
            *(float2*)&ctx[dst + 8 * DMOD] = make_float2(c[mt][nt][2] * iv1, c[mt][nt][3] * iv1);
        }
    }
}

// ---------------------------------------------------------------------------
// Residual + LayerNorm with warp-shuffle reductions.  grid 4096, block 256.
// ---------------------------------------------------------------------------
__global__ void ln_kernel(const float* __restrict__ resid,
                          const float* __restrict__ gamma,
                          const float* __restrict__ beta,
                          const float* __restrict__ fcv,
                          float* __restrict__ out)
{
    __shared__ float wsum[8];
    const int r = blockIdx.x;
    const float* xf = fcv + (size_t)r * DMOD;
    const float* rz = resid + (size_t)r * DMOD;
    const int t = threadIdx.x, lane = t & 31, w = t >> 5;

    float v[4];
    float sum = 0.f;
#pragma unroll
    for (int j = 0; j < 4; j++) {
        v[j] = xf[t + 256 * j] + rz[t + 256 * j];
        sum += v[j];
    }
#pragma unroll
    for (int o = 16; o > 0; o >>= 1) sum += __shfl_xor_sync(0xffffffffu, sum, o);
    if (lane == 0) wsum[w] = sum;
    __syncthreads();
    float tot = wsum[0];
#pragma unroll
    for (int j = 1; j < 8; j++) tot += wsum[j];
    const float mu = tot * (1.f / DMOD);

    float vs = 0.f;
#pragma unroll
    for (int j = 0; j < 4; j++) {
        const float d = v[j] - mu;
        vs += d * d;
    }
#pragma unroll
    for (int o = 16; o > 0; o >>= 1) vs += __shfl_xor_sync(0xffffffffu, vs, o);
    __syncthreads();           // wsum reuse
    if (lane == 0) wsum[w] = vs;
    __syncthreads();
    float vtot = wsum[0];
#pragma unroll
    for (int j = 1; j < 8; j++) vtot += wsum[j];
    const float var = vtot * (1.f / DMOD);
    const float inv = rsqrtf(var + 1e-5f);
#pragma unroll
    for (int j = 0; j < 4; j++) {
        const int cc = t + 256 * j;
        out[(size_t)r * DMOD + cc] = (v[j] - mu) * inv * gamma[cc] + beta[cc];
    }
}

// ---------------------------------------------------------------------------
extern "C" void kernel_launch(void* const* d_in, const int* in_sizes, int n_in,
                              void* d_out, int out_size)
{
    const float* q    = (const float*)d_in[0];
    const float* k    = (const float*)d_in[1];
    const float* v    = (const float*)d_in[2];
    const int*   mask = (const int*)  d_in[3];
    const float* gate = (const float*)d_in[4];
    const float* w_q  = (const float*)d_in[5];
    const float* b_q  = (const float*)d_in[6];
    const float* w_k  = (const float*)d_in[7];
    const float* b_k  = (const float*)d_in[8];
    const float* w_v  = (const float*)d_in[9];
    const float* b_v  = (const float*)d_in[10];
    const float* w_fc = (const float*)d_in[11];
    const float* b_fc = (const float*)d_in[12];
    const float* ln_g = (const float*)d_in[13];
    const float* ln_b = (const float*)d_in[14];
    float* out = (float*)d_out;

    float *p_qh, *p_kh, *p_vh, *p_ctx, *p_fc, *p_part, *p_inv, *p_attn_s, *p_outs;
    cudaGetSymbolAddress((void**)&p_qh,     g_qh);
    cudaGetSymbolAddress((void**)&p_kh,     g_kh);
    cudaGetSymbolAddress((void**)&p_vh,     g_vh);
    cudaGetSymbolAddress((void**)&p_ctx,    g_ctx);
    cudaGetSymbolAddress((void**)&p_fc,     g_fc);
    cudaGetSymbolAddress((void**)&p_part,   g_part);
    cudaGetSymbolAddress((void**)&p_inv,    g_invsum);
    cudaGetSymbolAddress((void**)&p_attn_s, g_attn);
    cudaGetSymbolAddress((void**)&p_outs,   g_outs);

    // Reference returns (out, attn).  Resolve destinations from out_size.
    float* attn_ptr;
    float* out_ptr;
    const long long osz = (long long)out_size;
    if (osz >= OUT_ELEMS + ATT_ELEMS) {        // concatenated tuple
        out_ptr  = out;
        attn_ptr = out + OUT_ELEMS;
    } else if (osz >= ATT_ELEMS) {             // attn only
        out_ptr  = p_outs;
        attn_ptr = out;
    } else {                                   // out only
        out_ptr  = out;
        attn_ptr = p_attn_s;
    }
    const int write_attn = (attn_ptr != p_attn_s) ? 1 : 0;

    // opt in to >48KB dynamic smem (idempotent)
    cudaFuncSetAttribute(gemm_v2, cudaFuncAttributeMaxDynamicSharedMemorySize,
                         GEMM_SMEM_BYTES);
    cudaFuncSetAttribute(gemm_qkv, cudaFuncAttributeMaxDynamicSharedMemorySize,
                         GEMM_SMEM_BYTES);
    cudaFuncSetAttribute(av_v4, cudaFuncAttributeMaxDynamicSharedMemorySize,
                         AV_SMEM_BYTES);

    // 1) QKV projections (merged: one launch, grid.z selects q/k/v)
    gemm_qkv<<<dim3(16, 32, 3), 256, GEMM_SMEM_BYTES>>>(
        q, k, v, w_q, w_k, w_v, b_q, b_k, b_v, p_qh, p_kh, p_vh);

    // 2) Scores + gate/mask + exp + partial row sums (unnormalized attn)
    scores_v5<<<dim3(16, 16, ZH), 256, SC_SMEM_BYTES>>>(p_qh, p_kh, gate, mask, attn_ptr, p_part);

    // 3) partials -> 1/rowsum
    reduce_inv<<<256, 256>>>(p_part, p_inv);

    // 4) AV: MMA unnormalized P, scale ctx; conditional normalized attn write
    av_v4<<<dim3(16, ZH), 256, AV_SMEM_BYTES>>>(attn_ptr, p_inv, p_vh, p_ctx, write_attn);

    // 5) FC projection
    gemm_v2<<<dim3(16, 32), 256, GEMM_SMEM_BYTES>>>(p_ctx, w_fc, b_fc, p_fc, DMOD, DMOD, DMOD);

    // 6) Residual + LayerNorm -> final out
    ln_kernel<<<4096, 256>>>(q, ln_g, ln_b, p_fc, out_ptr);
}

// round 15
// speedup vs baseline: 1.0986x; 1.0679x over previous
#include <cuda_runtime.h>
#include <math.h>

// Problem constants
#define BB 4
#define LS 1024
#define DMOD 1024
#define NH 16
#define DKH 64
#define DVH 64
#define ZH (BB * NH)

#define OUT_ELEMS ((long long)BB * LS * DMOD)            // 4194304
#define ATT_ELEMS ((long long)ZH * LS * LS)              // 67108864

// -------------------- scratch (device globals; no allocation allowed) ------
__device__ float g_qh[ZH * LS * DKH];        // [B,H,L,DK]
__device__ float g_kh[ZH * LS * DKH];
__device__ float g_vh[ZH * LS * DVH];
__device__ float g_ctx[BB * LS * NH * DVH];  // [B,L,H*DV]
__device__ float g_fc[BB * LS * DMOD];       // pre-LN fc output
__device__ float g_part[(size_t)ZH * LS * 16]; // per-(z,row) partial exp sums
__device__ float g_invsum[ZH * LS];          // 1 / rowsum
__device__ float g_attn[(size_t)ZH * LS * LS]; // attn scratch (fallback dest)
__device__ float g_outs[BB * LS * DMOD];     // fallback out sink

// ---------------------------------------------------------------------------
// helpers
// ---------------------------------------------------------------------------
__device__ __forceinline__ unsigned f2tf(float f) {
    unsigned r;
    asm("cvt.rna.tf32.f32 %0, %1;" : "=r"(r) : "f"(f));
    return r;
}

__device__ __forceinline__ void mma8(float& c0, float& c1, float& c2, float& c3,
                                     unsigned a0, unsigned a1, unsigned a2, unsigned a3,
                                     unsigned b0, unsigned b1) {
    asm volatile(
        "mma.sync.aligned.m16n8k8.row.col.f32.tf32.tf32.f32 "
        "{%0,%1,%2,%3}, {%4,%5,%6,%7}, {%8,%9}, {%0,%1,%2,%3};\n"
        : "+f"(c0), "+f"(c1), "+f"(c2), "+f"(c3)
        : "r"(a0), "r"(a1), "r"(a2), "r"(a3), "r"(b0), "r"(b1));
}

__device__ __forceinline__ void cpa16(void* s, const void* g) {
    asm volatile("cp.async.cg.shared.global [%0], [%1], 16;\n"
        :: "r"((unsigned)__cvta_generic_to_shared(s)), "l"(g) : "memory");
}
__device__ __forceinline__ void cpa_commit() {
    asm volatile("cp.async.commit_group;\n" ::: "memory");
}
template <int N> __device__ __forceinline__ void cpa_wait() {
    asm volatile("cp.async.wait_group %0;\n" :: "n"(N) : "memory");
}

// ---------------------------------------------------------------------------
// TF32 NT GEMM + bias, 128x128 tile, BK=32, cp.async double-buffered.
// 256 threads (8 warps, 2m x 4n, warp tile 64x32).  2 CTAs/SM.
// L2-traffic-optimal: A read N/128 times, W read M/128 times.
// ---------------------------------------------------------------------------
#define GEMM_SMEM_BYTES (2 * 2 * 128 * 36 * 4)   // 73728

__device__ __forceinline__ void gemm_xl_body(
    const float* __restrict__ A, const float* __restrict__ W,
    const float* __restrict__ bias, float* __restrict__ out,
    int K, int N, int Dhead, float* gsm)
{
    float* As = gsm;                 // 2 x (128 x 36)
    float* Ws = gsm + 2 * 128 * 36;  // 2 x (128 x 36)

    const int t = threadIdx.x, lane = t & 31, w = t >> 5;
    const int wm = w >> 2, wn = w & 3;          // 2m x 4n warps
    const int g = lane >> 2, tg = lane & 3;
    const int rowBase = blockIdx.y * 128;
    const int colBase = blockIdx.x * 128;

    const float* Ab = A + (size_t)rowBase * K;
    const float* Wb = W + (size_t)colBase * K;

    float c[4][4][4];
#pragma unroll
    for (int mt = 0; mt < 4; mt++)
#pragma unroll
        for (int nt = 0; nt < 4; nt++)
#pragma unroll
            for (int i = 0; i < 4; i++) c[mt][nt][i] = 0.f;

    const int nk = K >> 5;
    const int lrow = t >> 3, lc4 = (t & 7) * 4;   // loader: 128 rows x 32 cols

    {
#pragma unroll
        for (int i = 0; i < 4; i++) {
            const int row = lrow + ((i & 1) ? 0 : 0) + (i >> 0) * 0;  // placeholder
        }
    }
    // stage tile 0 (A and W: 4 float4 each per thread)
    {
#pragma unroll
        for (int i = 0; i < 4; i++) {
            const int idx4 = t + 256 * i;
            const int row = idx4 >> 3, c4 = (idx4 & 7) * 4;
            cpa16(&As[row * 36 + c4], Ab + (size_t)row * K + c4);
            cpa16(&Ws[row * 36 + c4], Wb + (size_t)row * K + c4);
        }
        cpa_commit();
    }

    for (int kt = 0; kt < nk; kt++) {
        if (kt + 1 < nk) {
            float* Ad = As + ((kt + 1) & 1) * (128 * 36);
            float* Wd = Ws + ((kt + 1) & 1) * (128 * 36);
            const int ko = (kt + 1) * 32;
#pragma unroll
            for (int i = 0; i < 4; i++) {
                const int idx4 = t + 256 * i;
                const int row = idx4 >> 3, c4 = (idx4 & 7) * 4;
                cpa16(&Ad[row * 36 + c4], Ab + (size_t)row * K + ko + c4);
                cpa16(&Wd[row * 36 + c4], Wb + (size_t)row * K + ko + c4);
            }
            cpa_commit();
            cpa_wait<1>();
        } else {
            cpa_wait<0>();
        }
        __syncthreads();

        const float* Ac = As + (kt & 1) * (128 * 36);
        const float* Wc = Ws + (kt & 1) * (128 * 36);
#pragma unroll
        for (int ks = 0; ks < 4; ks++) {
            const int kk = ks * 8;
            unsigned a[4][4], bf[4][2];
#pragma unroll
            for (int mt = 0; mt < 4; mt++) {
                const int r = (wm * 64 + mt * 16 + g) * 36 + kk + tg;
                a[mt][0] = f2tf(Ac[r]);
                a[mt][1] = f2tf(Ac[r + 8 * 36]);
                a[mt][2] = f2tf(Ac[r + 4]);
                a[mt][3] = f2tf(Ac[r + 8 * 36 + 4]);
            }
#pragma unroll
            for (int nt = 0; nt < 4; nt++) {
                const int r = (wn * 32 + nt * 8 + g) * 36 + kk + tg;
                bf[nt][0] = f2tf(Wc[r]);
                bf[nt][1] = f2tf(Wc[r + 4]);
            }
#pragma unroll
            for (int mt = 0; mt < 4; mt++)
#pragma unroll
                for (int nt = 0; nt < 4; nt++)
                    mma8(c[mt][nt][0], c[mt][nt][1], c[mt][nt][2], c[mt][nt][3],
                         a[mt][0], a[mt][1], a[mt][2], a[mt][3],
                         bf[nt][0], bf[nt][1]);
        }
        __syncthreads();
    }

    const int H = N / Dhead;
#pragma unroll
    for (int mt = 0; mt < 4; mt++) {
        const int rr = rowBase + wm * 64 + mt * 16 + g;
        const int b_ = rr >> 10, l = rr & 1023;
#pragma unroll
        for (int nt = 0; nt < 4; nt++) {
            const int cc = colBase + wn * 32 + nt * 8 + 2 * tg;
            const int h = cc / Dhead, d = cc % Dhead;
            const size_t dst = (((size_t)(b_ * H + h)) * LS + l) * Dhead + d;
            const float b0 = bias[cc], b1 = bias[cc + 1];
            *(float2*)&out[dst]             = make_float2(c[mt][nt][0] + b0, c[mt][nt][1] + b1);
            *(float2*)&out[dst + 8 * Dhead] = make_float2(c[mt][nt][2] + b0, c[mt][nt][3] + b1);
        }
    }
}

__global__ void __launch_bounds__(256, 2)
gemm_xl(const float* __restrict__ A, const float* __restrict__ W,
        const float* __restrict__ bias, float* __restrict__ out,
        int K, int N, int Dhead)
{
    extern __shared__ float gsm[];
    gemm_xl_body(A, W, bias, out, K, N, Dhead, gsm);
}

__global__ void __launch_bounds__(256, 2)
gemm_qkv_xl(const float* __restrict__ q, const float* __restrict__ k,
            const float* __restrict__ v,
            const float* __restrict__ w_q, const float* __restrict__ w_k,
            const float* __restrict__ w_v,
            const float* __restrict__ b_q, const float* __restrict__ b_k,
            const float* __restrict__ b_v,
            float* __restrict__ oq, float* __restrict__ ok, float* __restrict__ ov)
{
    extern __shared__ float gsm[];
    const int zz = blockIdx.z;
    const float* A  = (zz == 0) ? q   : (zz == 1) ? k   : v;
    const float* W  = (zz == 0) ? w_q : (zz == 1) ? w_k : w_v;
    const float* bi = (zz == 0) ? b_q : (zz == 1) ? b_k : b_v;
    float*       o  = (zz == 0) ? oq  : (zz == 1) ? ok  : ov;
    gemm_xl_body(A, W, bi, o, DMOD, NH * DKH, DKH, gsm);
}

// ---------------------------------------------------------------------------
// Scores v5 (round 11 exact): tile 64x64, 4 CTAs/SM, coalesced epilogue.
// ---------------------------------------------------------------------------
#define SC_SMEM_BYTES (2 * 64 * 68 * 4)

__global__ void __launch_bounds__(256, 4)
scores_v5(const float* __restrict__ qh, const float* __restrict__ kh,
          const float* __restrict__ gate, const int* __restrict__ mask,
          float* __restrict__ attn, float* __restrict__ part)
{
    extern __shared__ float ssm[];
    float* Qs  = ssm;                  // 64 x 68 (later aliased as Ss)
    float* Ksm = ssm + 64 * 68;        // 64 x 68 (later aliased as redsh)

    const int t = threadIdx.x, lane = t & 31, w = t >> 5;
    const int wm = w >> 2, wn = w & 3;     // 2m x 4n warps, warp tile 32x16
    const int g = lane >> 2, tg = lane & 3;
    const int z = blockIdx.z, b = z >> 4;
    const int qBase = blockIdx.y * 64;
    const int kBase = blockIdx.x * 64;

    const float* Q  = qh + (size_t)z * (LS * DKH) + qBase * DKH;
    const float* Kp = kh + (size_t)z * (LS * DKH) + kBase * DKH;

    {
        const int row = t >> 4, c = (t & 15) * 4;
        const int so = row * 68 + c;
        const int go = row * DKH + c;
#pragma unroll
        for (int i = 0; i < 4; i++) {
            cpa16(&Qs[so + i * 16 * 68], Q + go + i * 16 * DKH);
            cpa16(&Ksm[so + i * 16 * 68], Kp + go + i * 16 * DKH);
        }
    }
    cpa_commit();
    cpa_wait<0>();
    __syncthreads();

    float s[2][2][4];
#pragma unroll
    for (int mt = 0; mt < 2; mt++)
#pragma unroll
        for (int nt = 0; nt < 2; nt++)
#pragma unroll
            for (int i = 0; i < 4; i++) s[mt][nt][i] = 0.f;

    const int abase = (wm * 32 + g) * 68 + tg;
    const int bbase = (wn * 16 + g) * 68 + tg;
#pragma unroll
    for (int ks = 0; ks < 8; ks++) {
        const int kk = ks * 8;
        unsigned a[2][4], bf[2][2];
#pragma unroll
        for (int mt = 0; mt < 2; mt++) {
            const int r = abase + mt * (16 * 68) + kk;
            a[mt][0] = f2tf(Qs[r]);
            a[mt][1] = f2tf(Qs[r + 8 * 68]);
            a[mt][2] = f2tf(Qs[r + 4]);
            a[mt][3] = f2tf(Qs[r + 8 * 68 + 4]);
        }
#pragma unroll
        for (int nt = 0; nt < 2; nt++) {
            const int r = bbase + nt * (8 * 68) + kk;
            bf[nt][0] = f2tf(Ksm[r]);
            bf[nt][1] = f2tf(Ksm[r + 4]);
        }
#pragma unroll
        for (int mt = 0; mt < 2; mt++)
#pragma unroll
            for (int nt = 0; nt < 2; nt++)
                mma8(s[mt][nt][0], s[mt][nt][1], s[mt][nt][2], s[mt][nt][3],
                     a[mt][0], a[mt][1], a[mt][2], a[mt][3],
                     bf[nt][0], bf[nt][1]);
    }

    __syncthreads();   // Q/K smem reads done; safe to alias

    float* Ss = Qs;
    {
        const int rb = wm * 32 + g;
        const int cb = wn * 16 + 2 * tg;
#pragma unroll
        for (int mt = 0; mt < 2; mt++) {
            const int ro = (rb + mt * 16) * 68;
#pragma unroll
            for (int nt = 0; nt < 2; nt++) {
                const int col = cb + nt * 8;
                *(float2*)&Ss[ro + col]          = make_float2(s[mt][nt][0], s[mt][nt][1]);
                *(float2*)&Ss[ro + 8 * 68 + col] = make_float2(s[mt][nt][2], s[mt][nt][3]);
            }
        }
    }
    __syncthreads();

    float* redsh = Ksm;
    {
        const int row0 = t >> 4, c4 = (t & 15) * 4;
        const size_t rowcol = (size_t)(qBase + row0) * LS + kBase + c4;
        const float* gp = gate + (size_t)z * (LS * LS) + rowcol;
        const int*   mp = mask + (size_t)b * (LS * LS) + rowcol;
        float*       ap = attn + (size_t)z * (LS * LS) + rowcol;
        int so = row0 * 68 + c4;
#pragma unroll
        for (int i = 0; i < 4; i++) {
            float4 sv = *(float4*)&Ss[so];
            float4 gv = *(const float4*)gp;
            int4   mv = *(const int4*)mp;
            float4 ev;
            ev.x = (mv.x > 0) ? 0.f : __expf(sv.x * 0.125f * gv.x);
            ev.y = (mv.y > 0) ? 0.f : __expf(sv.y * 0.125f * gv.y);
            ev.z = (mv.z > 0) ? 0.f : __expf(sv.z * 0.125f * gv.z);
            ev.w = (mv.w > 0) ? 0.f : __expf(sv.w * 0.125f * gv.w);
            *(float4*)ap = ev;
            float sum = (ev.x + ev.y) + (ev.z + ev.w);
            sum += __shfl_xor_sync(0xffffffffu, sum, 1);
            sum += __shfl_xor_sync(0xffffffffu, sum, 2);
            sum += __shfl_xor_sync(0xffffffffu, sum, 4);
            sum += __shfl_xor_sync(0xffffffffu, sum, 8);
            if ((lane & 15) == 0) redsh[row0 + 16 * i] = sum;
            so += 16 * 68;
            gp += 16 * LS; mp += 16 * LS; ap += 16 * LS;
        }
    }
    __syncthreads();
    if (t < 64)
        part[((size_t)z * LS + qBase + t) * 16 + blockIdx.x] = redsh[t];
}

// ---------------------------------------------------------------------------
// Reduce 16 partials -> 1/rowsum.  grid 256, block 256.
// ---------------------------------------------------------------------------
__global__ void reduce_inv(const float* __restrict__ part, float* __restrict__ invsum)
{
    const int i = blockIdx.x * 256 + threadIdx.x;   // 65536 rows
    float s = 0.f;
#pragma unroll
    for (int j = 0; j < 16; j++) s += part[(size_t)i * 16 + j];
    invsum[i] = 1.f / s;
}

// ---------------------------------------------------------------------------
// AV v4 (round 11 exact): tile 64x64, BK=64, P+V cp.async double-buffered,
// MMA on unnormalized P, ctx scaled at end, conditional attn write-back.
// ---------------------------------------------------------------------------
#define AV_SMEM_BYTES ((2 * 64 * 68 + 2 * 64 * 72) * 4)

__global__ void __launch_bounds__(256, 3)
av_v4(float* __restrict__ attn, const float* __restrict__ invsum,
      const float* __restrict__ vh, float* __restrict__ ctx, int write_attn)
{
    extern __shared__ float avsm[];
    float* Ps = avsm;                   // 2 x (64 x 68)
    float* Vs = avsm + 2 * 64 * 68;     // 2 x (64 x 72)
    __shared__ float invsh[64];

    const int t = threadIdx.x, lane = t & 31, w = t >> 5;
    const int wm = w >> 2, wn = w & 3;     // 2m x 4n warps, warp tile 32x16
    const int g = lane >> 2, tg = lane & 3;
    const int z = blockIdx.y, b = z >> 4, h = z & 15;
    const int rowBase = blockIdx.x * 64;

    float* P = attn + (size_t)z * LS * LS + (size_t)rowBase * LS;
    const float* V = vh + (size_t)z * LS * DVH;

    if (t < 64) invsh[t] = invsum[z * LS + rowBase + t];

    int lr[4], lc[4];
#pragma unroll
    for (int i = 0; i < 4; i++) {
        const int idx4 = t + 256 * i;
        lr[i] = idx4 >> 4;
        lc[i] = (idx4 & 15) * 4;
    }

    float c[2][2][4];
#pragma unroll
    for (int mt = 0; mt < 2; mt++)
#pragma unroll
        for (int nt = 0; nt < 2; nt++)
#pragma unroll
            for (int i = 0; i < 4; i++) c[mt][nt][i] = 0.f;

#pragma unroll
    for (int i = 0; i < 4; i++) {
        cpa16(&Ps[lr[i] * 68 + lc[i]], P + (size_t)lr[i] * LS + lc[i]);
        cpa16(&Vs[lr[i] * 72 + lc[i]], V + (size_t)lr[i] * DVH + lc[i]);
    }
    cpa_commit();

    for (int kt = 0; kt < 16; kt++) {
        const bool more = (kt + 1 < 16);
        if (more) {
            const int ko = (kt + 1) * 64;
            float* Pd = Ps + ((kt + 1) & 1) * (64 * 68);
            float* Vd = Vs + ((kt + 1) & 1) * (64 * 72);
#pragma unroll
            for (int i = 0; i < 4; i++) {
                cpa16(&Pd[lr[i] * 68 + lc[i]], P + (size_t)lr[i] * LS + ko + lc[i]);
                cpa16(&Vd[lr[i] * 72 + lc[i]], V + (size_t)(ko + lr[i]) * DVH + lc[i]);
            }
            cpa_commit();
            cpa_wait<1>();
        } else {
            cpa_wait<0>();
        }
        __syncthreads();

        const float* Pc = Ps + (kt & 1) * (64 * 68);
        const float* Vc = Vs + (kt & 1) * (64 * 72);

        if (write_attn) {
            const int ko = kt * 64;
#pragma unroll
            for (int i = 0; i < 4; i++) {
                float4 pv = *(const float4*)&Pc[lr[i] * 68 + lc[i]];
                const float iv = invsh[lr[i]];
                pv.x *= iv; pv.y *= iv; pv.z *= iv; pv.w *= iv;
                *(float4*)(P + (size_t)lr[i] * LS + ko + lc[i]) = pv;
            }
        }

#pragma unroll
        for (int ks = 0; ks < 8; ks++) {
            const int kk = ks * 8;
            unsigned a[2][4], bf[2][2];
#pragma unroll
            for (int mt = 0; mt < 2; mt++) {
                const int r = (wm * 32 + mt * 16 + g) * 68 + kk + tg;
                a[mt][0] = f2tf(Pc[r]);
                a[mt][1] = f2tf(Pc[r + 8 * 68]);
                a[mt][2] = f2tf(Pc[r + 4]);
                a[mt][3] = f2tf(Pc[r + 8 * 68 + 4]);
            }
#pragma unroll
            for (int nt = 0; nt < 2; nt++) {
                const int col = wn * 16 + nt * 8 + g;
                bf[nt][0] = f2tf(Vc[(kk + tg) * 72 + col]);
                bf[nt][1] = f2tf(Vc[(kk + tg + 4) * 72 + col]);
            }
#pragma unroll
            for (int mt = 0; mt < 2; mt++)
#pragma unroll
                for (int nt = 0; nt < 2; nt++)
                    mma8(c[mt][nt][0], c[mt][nt][1], c[mt][nt][2], c[mt][nt][3],
                         a[mt][0], a[mt][1], a[mt][2], a[mt][3],
                         bf[nt][0], bf[nt][1]);
        }
        __syncthreads();
    }

#pragma unroll
    for (int mt = 0; mt < 2; mt++) {
        const int lrow = wm * 32 + mt * 16 + g;
        const int rr = rowBase + lrow;
        const float iv0 = invsh[lrow], iv1 = invsh[lrow + 8];
#pragma unroll
        for (int nt = 0; nt < 2; nt++) {
            const int d = wn * 16 + nt * 8 + 2 * tg;
            const size_t dst = ((size_t)(b * LS + rr)) * DMOD + h * 64 + d;
            *(float2*)&ctx[dst]            = make_float2(c[mt][nt][0] * iv0, c[mt][nt][1] * iv0);
            *(float2*)&ctx[dst + 8 * DMOD] = make_float2(c[mt][nt][2] * iv1, c[mt][nt][3] * iv1);
        }
    }
}

// ---------------------------------------------------------------------------
// Residual + LayerNorm (round 11 tree version).  grid 4096, block 256.
// ---------------------------------------------------------------------------
__global__ void ln_kernel(const float* __restrict__ resid,
                          const float* __restrict__ gamma,
                          const float* __restrict__ beta,
                          const float* __restrict__ fcv,
                          float* __restrict__ out)
{
    __shared__ float red[256];
    const int r = blockIdx.x;
    const float* xf = fcv + (size_t)r * DMOD;
    const float* rz = resid + (size_t)r * DMOD;
    const int t = threadIdx.x;

    float v[4];
    float sum = 0.f;
#pragma unroll
    for (int j = 0; j < 4; j++) {
        v[j] = xf[t + 256 * j] + rz[t + 256 * j];
        sum += v[j];
    }
    red[t] = sum; __syncthreads();
    for (int s = 128; s > 0; s >>= 1) {
        if (t < s) red[t] += red[t + s];
        __syncthreads();
    }
    const float mu = red[0] * (1.f / DMOD);
    __syncthreads();

    float vs = 0.f;
#pragma unroll
    for (int j = 0; j < 4; j++) {
        const float d = v[j] - mu;
        vs += d * d;
    }
    red[t] = vs; __syncthreads();
    for (int s = 128; s > 0; s >>= 1) {
        if (t < s) red[t] += red[t + s];
        __syncthreads();
    }
    const float var = red[0] * (1.f / DMOD);
    const float inv = rsqrtf(var + 1e-5f);
#pragma unroll
    for (int j = 0; j < 4; j++) {
        const int cc = t + 256 * j;
        out[(size_t)r * DMOD + cc] = (v[j] - mu) * inv * gamma[cc] + beta[cc];
    }
}

// ---------------------------------------------------------------------------
extern "C" void kernel_launch(void* const* d_in, const int* in_sizes, int n_in,
                              void* d_out, int out_size)
{
    const float* q    = (const float*)d_in[0];
    const float* k    = (const float*)d_in[1];
    const float* v    = (const float*)d_in[2];
    const int*   mask = (const int*)  d_in[3];
    const float* gate = (const float*)d_in[4];
    const float* w_q  = (const float*)d_in[5];
    const float* b_q  = (const float*)d_in[6];
    const float* w_k  = (const float*)d_in[7];
    const float* b_k  = (const float*)d_in[8];
    const float* w_v  = (const float*)d_in[9];
    const float* b_v  = (const float*)d_in[10];
    const float* w_fc = (const float*)d_in[11];
    const float* b_fc = (const float*)d_in[12];
    const float* ln_g = (const float*)d_in[13];
    const float* ln_b = (const float*)d_in[14];
    float* out = (float*)d_out;

    float *p_qh, *p_kh, *p_vh, *p_ctx, *p_fc, *p_part, *p_inv, *p_attn_s, *p_outs;
    cudaGetSymbolAddress((void**)&p_qh,     g_qh);
    cudaGetSymbolAddress((void**)&p_kh,     g_kh);
    cudaGetSymbolAddress((void**)&p_vh,     g_vh);
    cudaGetSymbolAddress((void**)&p_ctx,    g_ctx);
    cudaGetSymbolAddress((void**)&p_fc,     g_fc);
    cudaGetSymbolAddress((void**)&p_part,   g_part);
    cudaGetSymbolAddress((void**)&p_inv,    g_invsum);
    cudaGetSymbolAddress((void**)&p_attn_s, g_attn);
    cudaGetSymbolAddress((void**)&p_outs,   g_outs);

    // Reference returns (out, attn).  Resolve destinations from out_size.
    float* attn_ptr;
    float* out_ptr;
    const long long osz = (long long)out_size;
    if (osz >= OUT_ELEMS + ATT_ELEMS) {        // concatenated tuple
        out_ptr  = out;
        attn_ptr = out + OUT_ELEMS;
    } else if (osz >= ATT_ELEMS) {             // attn only
        out_ptr  = p_outs;
        attn_ptr = out;
    } else {                                   // out only
        out_ptr  = out;
        attn_ptr = p_attn_s;
    }
    const int write_attn = (attn_ptr != p_attn_s) ? 1 : 0;

    // opt in to >48KB dynamic smem (idempotent)
    cudaFuncSetAttribute(gemm_xl, cudaFuncAttributeMaxDynamicSharedMemorySize,
                         GEMM_SMEM_BYTES);
    cudaFuncSetAttribute(gemm_qkv_xl, cudaFuncAttributeMaxDynamicSharedMemorySize,
                         GEMM_SMEM_BYTES);
    cudaFuncSetAttribute(av_v4, cudaFuncAttributeMaxDynamicSharedMemorySize,
                         AV_SMEM_BYTES);

    // 1) QKV projections (merged, 128x128 tiles)
    gemm_qkv_xl<<<dim3(8, 32, 3), 256, GEMM_SMEM_BYTES>>>(
        q, k, v, w_q, w_k, w_v, b_q, b_k, b_v, p_qh, p_kh, p_vh);

    // 2) Scores + gate/mask + exp + partial row sums (unnormalized attn)
    scores_v5<<<dim3(16, 16, ZH), 256, SC_SMEM_BYTES>>>(p_qh, p_kh, gate, mask, attn_ptr, p_part);

    // 3) partials -> 1/rowsum
    reduce_inv<<<256, 256>>>(p_part, p_inv);

    // 4) AV: MMA unnormalized P, scale ctx; conditional normalized attn write
    av_v4<<<dim3(16, ZH), 256, AV_SMEM_BYTES>>>(attn_ptr, p_inv, p_vh, p_ctx, write_attn);

    // 5) FC projection (128x128 tiles)
    gemm_xl<<<dim3(8, 32), 256, GEMM_SMEM_BYTES>>>(p_ctx, w_fc, b_fc, p_fc, DMOD, DMOD, DMOD);

    // 6) Residual + LayerNorm -> final out
    ln_kernel<<<4096, 256>>>(q, ln_g, ln_b, p_fc, out_ptr);
}

// round 16
// speedup vs baseline: 1.1135x; 1.0136x over previous
#include <cuda_runtime.h>
#include <math.h>

// Problem constants
#define BB 4
#define LS 1024
#define DMOD 1024
#define NH 16
#define DKH 64
#define DVH 64
#define ZH (BB * NH)

#define OUT_ELEMS ((long long)BB * LS * DMOD)            // 4194304
#define ATT_ELEMS ((long long)ZH * LS * LS)              // 67108864

// -------------------- scratch (device globals; no allocation allowed) ------
__device__ float g_qh[ZH * LS * DKH];        // [B,H,L,DK]
__device__ float g_kh[ZH * LS * DKH];
__device__ float g_vh[ZH * LS * DVH];
__device__ float g_ctx[BB * LS * NH * DVH];  // [B,L,H*DV]
__device__ float g_fc[BB * LS * DMOD];       // pre-LN fc output
__device__ float g_part[(size_t)ZH * LS * 16]; // per-(z,row) partial exp sums
__device__ float g_attn[(size_t)ZH * LS * LS]; // attn scratch (fallback dest)
__device__ float g_outs[BB * LS * DMOD];     // fallback out sink

// ---------------------------------------------------------------------------
// helpers
// ---------------------------------------------------------------------------
__device__ __forceinline__ unsigned f2tf(float f) {
    unsigned r;
    asm("cvt.rna.tf32.f32 %0, %1;" : "=r"(r) : "f"(f));
    return r;
}

__device__ __forceinline__ void mma8(float& c0, float& c1, float& c2, float& c3,
                                     unsigned a0, unsigned a1, unsigned a2, unsigned a3,
                                     unsigned b0, unsigned b1) {
    asm volatile(
        "mma.sync.aligned.m16n8k8.row.col.f32.tf32.tf32.f32 "
        "{%0,%1,%2,%3}, {%4,%5,%6,%7}, {%8,%9}, {%0,%1,%2,%3};\n"
        : "+f"(c0), "+f"(c1), "+f"(c2), "+f"(c3)
        : "r"(a0), "r"(a1), "r"(a2), "r"(a3), "r"(b0), "r"(b1));
}

__device__ __forceinline__ void cpa16(void* s, const void* g) {
    asm volatile("cp.async.cg.shared.global [%0], [%1], 16;\n"
        :: "r"((unsigned)__cvta_generic_to_shared(s)), "l"(g) : "memory");
}
__device__ __forceinline__ void cpa_commit() {
    asm volatile("cp.async.commit_group;\n" ::: "memory");
}
template <int N> __device__ __forceinline__ void cpa_wait() {
    asm volatile("cp.async.wait_group %0;\n" :: "n"(N) : "memory");
}

// ---------------------------------------------------------------------------
// TF32 NT GEMM + bias, 128x128 tile, BK=32, cp.async double-buffered.
// 256 threads (8 warps, 2m x 4n, warp tile 64x32).  2 CTAs/SM.
// ---------------------------------------------------------------------------
#define GEMM_SMEM_BYTES (2 * 2 * 128 * 36 * 4)   // 73728

__device__ __forceinline__ void gemm_xl_body(
    const float* __restrict__ A, const float* __restrict__ W,
    const float* __restrict__ bias, float* __restrict__ out,
    int K, int N, int Dhead, float* gsm)
{
    float* As = gsm;                 // 2 x (128 x 36)
    float* Ws = gsm + 2 * 128 * 36;  // 2 x (128 x 36)

    const int t = threadIdx.x, lane = t & 31, w = t >> 5;
    const int wm = w >> 2, wn = w & 3;          // 2m x 4n warps
    const int g = lane >> 2, tg = lane & 3;
    const int rowBase = blockIdx.y * 128;
    const int colBase = blockIdx.x * 128;

    const float* Ab = A + (size_t)rowBase * K;
    const float* Wb = W + (size_t)colBase * K;

    float c[4][4][4];
#pragma unroll
    for (int mt = 0; mt < 4; mt++)
#pragma unroll
        for (int nt = 0; nt < 4; nt++)
#pragma unroll
            for (int i = 0; i < 4; i++) c[mt][nt][i] = 0.f;

    const int nk = K >> 5;

    // stage tile 0 (A and W: 4 float4 each per thread)
    {
#pragma unroll
        for (int i = 0; i < 4; i++) {
            const int idx4 = t + 256 * i;
            const int row = idx4 >> 3, c4 = (idx4 & 7) * 4;
            cpa16(&As[row * 36 + c4], Ab + (size_t)row * K + c4);
            cpa16(&Ws[row * 36 + c4], Wb + (size_t)row * K + c4);
        }
        cpa_commit();
    }

    for (int kt = 0; kt < nk; kt++) {
        if (kt + 1 < nk) {
            float* Ad = As + ((kt + 1) & 1) * (128 * 36);
            float* Wd = Ws + ((kt + 1) & 1) * (128 * 36);
            const int ko = (kt + 1) * 32;
#pragma unroll
            for (int i = 0; i < 4; i++) {
                const int idx4 = t + 256 * i;
                const int row = idx4 >> 3, c4 = (idx4 & 7) * 4;
                cpa16(&Ad[row * 36 + c4], Ab + (size_t)row * K + ko + c4);
                cpa16(&Wd[row * 36 + c4], Wb + (size_t)row * K + ko + c4);
            }
            cpa_commit();
            cpa_wait<1>();
        } else {
            cpa_wait<0>();
        }
        __syncthreads();

        const float* Ac = As + (kt & 1) * (128 * 36);
        const float* Wc = Ws + (kt & 1) * (128 * 36);
#pragma unroll
        for (int ks = 0; ks < 4; ks++) {
            const int kk = ks * 8;
            unsigned a[4][4], bf[4][2];
#pragma unroll
            for (int mt = 0; mt < 4; mt++) {
                const int r = (wm * 64 + mt * 16 + g) * 36 + kk + tg;
                a[mt][0] = f2tf(Ac[r]);
                a[mt][1] = f2tf(Ac[r + 8 * 36]);
                a[mt][2] = f2tf(Ac[r + 4]);
                a[mt][3] = f2tf(Ac[r + 8 * 36 + 4]);
            }
#pragma unroll
            for (int nt = 0; nt < 4; nt++) {
                const int r = (wn * 32 + nt * 8 + g) * 36 + kk + tg;
                bf[nt][0] = f2tf(Wc[r]);
                bf[nt][1] = f2tf(Wc[r + 4]);
            }
#pragma unroll
            for (int mt = 0; mt < 4; mt++)
#pragma unroll
                for (int nt = 0; nt < 4; nt++)
                    mma8(c[mt][nt][0], c[mt][nt][1], c[mt][nt][2], c[mt][nt][3],
                         a[mt][0], a[mt][1], a[mt][2], a[mt][3],
                         bf[nt][0], bf[nt][1]);
        }
        __syncthreads();
    }

    const int H = N / Dhead;
#pragma unroll
    for (int mt = 0; mt < 4; mt++) {
        const int rr = rowBase + wm * 64 + mt * 16 + g;
        const int b_ = rr >> 10, l = rr & 1023;
#pragma unroll
        for (int nt = 0; nt < 4; nt++) {
            const int cc = colBase + wn * 32 + nt * 8 + 2 * tg;
            const int h = cc / Dhead, d = cc % Dhead;
            const size_t dst = (((size_t)(b_ * H + h)) * LS + l) * Dhead + d;
            const float b0 = bias[cc], b1 = bias[cc + 1];
            *(float2*)&out[dst]             = make_float2(c[mt][nt][0] + b0, c[mt][nt][1] + b1);
            *(float2*)&out[dst + 8 * Dhead] = make_float2(c[mt][nt][2] + b0, c[mt][nt][3] + b1);
        }
    }
}

__global__ void __launch_bounds__(256, 2)
gemm_xl(const float* __restrict__ A, const float* __restrict__ W,
        const float* __restrict__ bias, float* __restrict__ out,
        int K, int N, int Dhead)
{
    extern __shared__ float gsm[];
    gemm_xl_body(A, W, bias, out, K, N, Dhead, gsm);
}

__global__ void __launch_bounds__(256, 2)
gemm_qkv_xl(const float* __restrict__ q, const float* __restrict__ k,
            const float* __restrict__ v,
            const float* __restrict__ w_q, const float* __restrict__ w_k,
            const float* __restrict__ w_v,
            const float* __restrict__ b_q, const float* __restrict__ b_k,
            const float* __restrict__ b_v,
            float* __restrict__ oq, float* __restrict__ ok, float* __restrict__ ov)
{
    extern __shared__ float gsm[];
    const int zz = blockIdx.z;
    const float* A  = (zz == 0) ? q   : (zz == 1) ? k   : v;
    const float* W  = (zz == 0) ? w_q : (zz == 1) ? w_k : w_v;
    const float* bi = (zz == 0) ? b_q : (zz == 1) ? b_k : b_v;
    float*       o  = (zz == 0) ? oq  : (zz == 1) ? ok  : ov;
    gemm_xl_body(A, W, bi, o, DMOD, NH * DKH, DKH, gsm);
}

// ---------------------------------------------------------------------------
// Scores v5 (round 11 exact): tile 64x64, 4 CTAs/SM, coalesced epilogue.
// ---------------------------------------------------------------------------
#define SC_SMEM_BYTES (2 * 64 * 68 * 4)

__global__ void __launch_bounds__(256, 4)
scores_v5(const float* __restrict__ qh, const float* __restrict__ kh,
          const float* __restrict__ gate, const int* __restrict__ mask,
          float* __restrict__ attn, float* __restrict__ part)
{
    extern __shared__ float ssm[];
    float* Qs  = ssm;                  // 64 x 68 (later aliased as Ss)
    float* Ksm = ssm + 64 * 68;        // 64 x 68 (later aliased as redsh)

    const int t = threadIdx.x, lane = t & 31, w = t >> 5;
    const int wm = w >> 2, wn = w & 3;     // 2m x 4n warps, warp tile 32x16
    const int g = lane >> 2, tg = lane & 3;
    const int z = blockIdx.z, b = z >> 4;
    const int qBase = blockIdx.y * 64;
    const int kBase = blockIdx.x * 64;

    const float* Q  = qh + (size_t)z * (LS * DKH) + qBase * DKH;
    const float* Kp = kh + (size_t)z * (LS * DKH) + kBase * DKH;

    {
        const int row = t >> 4, c = (t & 15) * 4;
        const int so = row * 68 + c;
        const int go = row * DKH + c;
#pragma unroll
        for (int i = 0; i < 4; i++) {
            cpa16(&Qs[so + i * 16 * 68], Q + go + i * 16 * DKH);
            cpa16(&Ksm[so + i * 16 * 68], Kp + go + i * 16 * DKH);
        }
    }
    cpa_commit();
    cpa_wait<0>();
    __syncthreads();

    float s[2][2][4];
#pragma unroll
    for (int mt = 0; mt < 2; mt++)
#pragma unroll
        for (int nt = 0; nt < 2; nt++)
#pragma unroll
            for (int i = 0; i < 4; i++) s[mt][nt][i] = 0.f;

    const int abase = (wm * 32 + g) * 68 + tg;
    const int bbase = (wn * 16 + g) * 68 + tg;
#pragma unroll
    for (int ks = 0; ks < 8; ks++) {
        const int kk = ks * 8;
        unsigned a[2][4], bf[2][2];
#pragma unroll
        for (int mt = 0; mt < 2; mt++) {
            const int r = abase + mt * (16 * 68) + kk;
            a[mt][0] = f2tf(Qs[r]);
            a[mt][1] = f2tf(Qs[r + 8 * 68]);
            a[mt][2] = f2tf(Qs[r + 4]);
            a[mt][3] = f2tf(Qs[r + 8 * 68 + 4]);
        }
#pragma unroll
        for (int nt = 0; nt < 2; nt++) {
            const int r = bbase + nt * (8 * 68) + kk;
            bf[nt][0] = f2tf(Ksm[r]);
            bf[nt][1] = f2tf(Ksm[r + 4]);
        }
#pragma unroll
        for (int mt = 0; mt < 2; mt++)
#pragma unroll
            for (int nt = 0; nt < 2; nt++)
                mma8(s[mt][nt][0], s[mt][nt][1], s[mt][nt][2], s[mt][nt][3],
                     a[mt][0], a[mt][1], a[mt][2], a[mt][3],
                     bf[nt][0], bf[nt][1]);
    }

    __syncthreads();   // Q/K smem reads done; safe to alias

    float* Ss = Qs;
    {
        const int rb = wm * 32 + g;
        const int cb = wn * 16 + 2 * tg;
#pragma unroll
        for (int mt = 0; mt < 2; mt++) {
            const int ro = (rb + mt * 16) * 68;
#pragma unroll
            for (int nt = 0; nt < 2; nt++) {
                const int col = cb + nt * 8;
                *(float2*)&Ss[ro + col]          = make_float2(s[mt][nt][0], s[mt][nt][1]);
                *(float2*)&Ss[ro + 8 * 68 + col] = make_float2(s[mt][nt][2], s[mt][nt][3]);
            }
        }
    }
    __syncthreads();

    float* redsh = Ksm;
    {
        const int row0 = t >> 4, c4 = (t & 15) * 4;
        const size_t rowcol = (size_t)(qBase + row0) * LS + kBase + c4;
        const float* gp = gate + (size_t)z * (LS * LS) + rowcol;
        const int*   mp = mask + (size_t)b * (LS * LS) + rowcol;
        float*       ap = attn + (size_t)z * (LS * LS) + rowcol;
        int so = row0 * 68 + c4;
#pragma unroll
        for (int i = 0; i < 4; i++) {
            float4 sv = *(float4*)&Ss[so];
            float4 gv = *(const float4*)gp;
            int4   mv = *(const int4*)mp;
            float4 ev;
            ev.x = (mv.x > 0) ? 0.f : __expf(sv.x * 0.125f * gv.x);
            ev.y = (mv.y > 0) ? 0.f : __expf(sv.y * 0.125f * gv.y);
            ev.z = (mv.z > 0) ? 0.f : __expf(sv.z * 0.125f * gv.z);
            ev.w = (mv.w > 0) ? 0.f : __expf(sv.w * 0.125f * gv.w);
            *(float4*)ap = ev;
            float sum = (ev.x + ev.y) + (ev.z + ev.w);
            sum += __shfl_xor_sync(0xffffffffu, sum, 1);
            sum += __shfl_xor_sync(0xffffffffu, sum, 2);
            sum += __shfl_xor_sync(0xffffffffu, sum, 4);
            sum += __shfl_xor_sync(0xffffffffu, sum, 8);
            if ((lane & 15) == 0) redsh[row0 + 16 * i] = sum;
            so += 16 * 68;
            gp += 16 * LS; mp += 16 * LS; ap += 16 * LS;
        }
    }
    __syncthreads();
    if (t < 64)
        part[((size_t)z * LS + qBase + t) * 16 + blockIdx.x] = redsh[t];
}

// ---------------------------------------------------------------------------
// AV v6: av_v4 + in-kernel invsum (each CTA is sole consumer of its rows)
// + __stcs on the terminal normalized-attn write.
// Tile 64x64, BK=64, P+V cp.async double-buffered, 3 CTAs/SM.
// ---------------------------------------------------------------------------
#define AV_SMEM_BYTES ((2 * 64 * 68 + 2 * 64 * 72) * 4)

__global__ void __launch_bounds__(256, 3)
av_v6(float* __restrict__ attn, const float* __restrict__ part,
      const float* __restrict__ vh, float* __restrict__ ctx, int write_attn)
{
    extern __shared__ float avsm[];
    float* Ps = avsm;                   // 2 x (64 x 68)
    float* Vs = avsm + 2 * 64 * 68;     // 2 x (64 x 72)
    __shared__ float invsh[64];

    const int t = threadIdx.x, lane = t & 31, w = t >> 5;
    const int wm = w >> 2, wn = w & 3;     // 2m x 4n warps, warp tile 32x16
    const int g = lane >> 2, tg = lane & 3;
    const int z = blockIdx.y, b = z >> 4, h = z & 15;
    const int rowBase = blockIdx.x * 64;

    float* P = attn + (size_t)z * LS * LS + (size_t)rowBase * LS;
    const float* V = vh + (size_t)z * LS * DVH;

    // in-kernel invsum: same 16-partial sum order as reduce_inv (bit-identical)
    if (t < 64) {
        const float* pp = part + ((size_t)z * LS + rowBase + t) * 16;
        float s = 0.f;
#pragma unroll
        for (int j = 0; j < 16; j++) s += pp[j];
        invsh[t] = 1.f / s;
    }

    int lr[4], lc[4];
#pragma unroll
    for (int i = 0; i < 4; i++) {
        const int idx4 = t + 256 * i;
        lr[i] = idx4 >> 4;
        lc[i] = (idx4 & 15) * 4;
    }

    float c[2][2][4];
#pragma unroll
    for (int mt = 0; mt < 2; mt++)
#pragma unroll
        for (int nt = 0; nt < 2; nt++)
#pragma unroll
            for (int i = 0; i < 4; i++) c[mt][nt][i] = 0.f;

#pragma unroll
    for (int i = 0; i < 4; i++) {
        cpa16(&Ps[lr[i] * 68 + lc[i]], P + (size_t)lr[i] * LS + lc[i]);
        cpa16(&Vs[lr[i] * 72 + lc[i]], V + (size_t)lr[i] * DVH + lc[i]);
    }
    cpa_commit();

    for (int kt = 0; kt < 16; kt++) {
        const bool more = (kt + 1 < 16);
        if (more) {
            const int ko = (kt + 1) * 64;
            float* Pd = Ps + ((kt + 1) & 1) * (64 * 68);
            float* Vd = Vs + ((kt + 1) & 1) * (64 * 72);
#pragma unroll
            for (int i = 0; i < 4; i++) {
                cpa16(&Pd[lr[i] * 68 + lc[i]], P + (size_t)lr[i] * LS + ko + lc[i]);
                cpa16(&Vd[lr[i] * 72 + lc[i]], V + (size_t)(ko + lr[i]) * DVH + lc[i]);
            }
            cpa_commit();
            cpa_wait<1>();
        } else {
            cpa_wait<0>();
        }
        __syncthreads();   // also orders invsh writes before reads below

        const float* Pc = Ps + (kt & 1) * (64 * 68);
        const float* Vc = Vs + (kt & 1) * (64 * 72);

        if (write_attn) {
            const int ko = kt * 64;
#pragma unroll
            for (int i = 0; i < 4; i++) {
                float4 pv = *(const float4*)&Pc[lr[i] * 68 + lc[i]];
                const float iv = invsh[lr[i]];
                pv.x *= iv; pv.y *= iv; pv.z *= iv; pv.w *= iv;
                __stcs((float4*)(P + (size_t)lr[i] * LS + ko + lc[i]), pv);  // terminal write
            }
        }

#pragma unroll
        for (int ks = 0; ks < 8; ks++) {
            const int kk = ks * 8;
            unsigned a[2][4], bf[2][2];
#pragma unroll
            for (int mt = 0; mt < 2; mt++) {
                const int r = (wm * 32 + mt * 16 + g) * 68 + kk + tg;
                a[mt][0] = f2tf(Pc[r]);
                a[mt][1] = f2tf(Pc[r + 8 * 68]);
                a[mt][2] = f2tf(Pc[r + 4]);
                a[mt][3] = f2tf(Pc[r + 8 * 68 + 4]);
            }
#pragma unroll
            for (int nt = 0; nt < 2; nt++) {
                const int col = wn * 16 + nt * 8 + g;
                bf[nt][0] = f2tf(Vc[(kk + tg) * 72 + col]);
                bf[nt][1] = f2tf(Vc[(kk + tg + 4) * 72 + col]);
            }
#pragma unroll
            for (int mt = 0; mt < 2; mt++)
#pragma unroll
                for (int nt = 0; nt < 2; nt++)
                    mma8(c[mt][nt][0], c[mt][nt][1], c[mt][nt][2], c[mt][nt][3],
                         a[mt][0], a[mt][1], a[mt][2], a[mt][3],
                         bf[nt][0], bf[nt][1]);
        }
        __syncthreads();
    }

#pragma unroll
    for (int mt = 0; mt < 2; mt++) {
        const int lrow = wm * 32 + mt * 16 + g;
        const int rr = rowBase + lrow;
        const float iv0 = invsh[lrow], iv1 = invsh[lrow + 8];
#pragma unroll
        for (int nt = 0; nt < 2; nt++) {
            const int d = wn * 16 + nt * 8 + 2 * tg;
            const size_t dst = ((size_t)(b * LS + rr)) * DMOD + h * 64 + d;
            *(float2*)&ctx[dst]            = make_float2(c[mt][nt][0] * iv0, c[mt][nt][1] * iv0);
            *(float2*)&ctx[dst + 8 * DMOD] = make_float2(c[mt][nt][2] * iv1, c[mt][nt][3] * iv1);
        }
    }
}

// ---------------------------------------------------------------------------
// LN: one warp per row, pure shuffle reductions, no block barriers.
// grid 512, block 256 (8 warps = 8 rows).
// ---------------------------------------------------------------------------
__global__ void __launch_bounds__(256)
ln_warp(const float* __restrict__ resid,
        const float* __restrict__ gamma,
        const float* __restrict__ beta,
        const float* __restrict__ fcv,
        float* __restrict__ out)
{
    const int lane = threadIdx.x & 31, w = threadIdx.x >> 5;
    const int r = blockIdx.x * 8 + w;
    const float4* xf = (const float4*)(fcv   + (size_t)r * DMOD);
    const float4* rz = (const float4*)(resid + (size_t)r * DMOD);
    const float4* gm = (const float4*)gamma;
    const float4* bt = (const float4*)beta;
    float4* op = (float4*)(out + (size_t)r * DMOD);

    float4 v[8];
    float sum = 0.f;
#pragma unroll
    for (int i = 0; i < 8; i++) {
        float4 a = xf[lane + 32 * i];
        float4 b = rz[lane + 32 * i];
        v[i] = make_float4(a.x + b.x, a.y + b.y, a.z + b.z, a.w + b.w);
        sum += (v[i].x + v[i].y) + (v[i].z + v[i].w);
    }
#pragma unroll
    for (int o = 16; o > 0; o >>= 1) sum += __shfl_xor_sync(0xffffffffu, sum, o);
    const float mu = sum * (1.f / DMOD);

    float vs = 0.f;
#pragma unroll
    for (int i = 0; i < 8; i++) {
        float dx = v[i].x - mu, dy = v[i].y - mu, dz = v[i].z - mu, dw = v[i].w - mu;
        vs += (dx * dx + dy * dy) + (dz * dz + dw * dw);
    }
#pragma unroll
    for (int o = 16; o > 0; o >>= 1) vs += __shfl_xor_sync(0xffffffffu, vs, o);
    const float inv = rsqrtf(vs * (1.f / DMOD) + 1e-5f);

#pragma unroll
    for (int i = 0; i < 8; i++) {
        float4 gv = gm[lane + 32 * i];
        float4 bv = bt[lane + 32 * i];
        float4 ov;
        ov.x = (v[i].x - mu) * inv * gv.x + bv.x;
        ov.y = (v[i].y - mu) * inv * gv.y + bv.y;
        ov.z = (v[i].z - mu) * inv * gv.z + bv.z;
        ov.w = (v[i].w - mu) * inv * gv.w + bv.w;
        op[lane + 32 * i] = ov;
    }
}

// ---------------------------------------------------------------------------
extern "C" void kernel_launch(void* const* d_in, const int* in_sizes, int n_in,
                              void* d_out, int out_size)
{
    const float* q    = (const float*)d_in[0];
    const float* k    = (const float*)d_in[1];
    const float* v    = (const float*)d_in[2];
    const int*   mask = (const int*)  d_in[3];
    const float* gate = (const float*)d_in[4];
    const float* w_q  = (const float*)d_in[5];
    const float* b_q  = (const float*)d_in[6];
    const float* w_k  = (const float*)d_in[7];
    const float* b_k  = (const float*)d_in[8];
    const float* w_v  = (const float*)d_in[9];
    const float* b_v  = (const float*)d_in[10];
    const float* w_fc = (const float*)d_in[11];
    const float* b_fc = (const float*)d_in[12];
    const float* ln_g = (const float*)d_in[13];
    const float* ln_b = (const float*)d_in[14];
    float* out = (float*)d_out;

    float *p_qh, *p_kh, *p_vh, *p_ctx, *p_fc, *p_part, *p_attn_s, *p_outs;
    cudaGetSymbolAddress((void**)&p_qh,     g_qh);
    cudaGetSymbolAddress((void**)&p_kh,     g_kh);
    cudaGetSymbolAddress((void**)&p_vh,     g_vh);
    cudaGetSymbolAddress((void**)&p_ctx,    g_ctx);
    cudaGetSymbolAddress((void**)&p_fc,     g_fc);
    cudaGetSymbolAddress((void**)&p_part,   g_part);
    cudaGetSymbolAddress((void**)&p_attn_s, g_attn);
    cudaGetSymbolAddress((void**)&p_outs,   g_outs);

    // Reference returns (out, attn).  Resolve destinations from out_size.
    float* attn_ptr;
    float* out_ptr;
    const long long osz = (long long)out_size;
    if (osz >= OUT_ELEMS + ATT_ELEMS) {        // concatenated tuple
        out_ptr  = out;
        attn_ptr = out + OUT_ELEMS;
    } else if (osz >= ATT_ELEMS) {             // attn only
        out_ptr  = p_outs;
        attn_ptr = out;
    } else {                                   // out only
        out_ptr  = out;
        attn_ptr = p_attn_s;
    }
    const int write_attn = (attn_ptr != p_attn_s) ? 1 : 0;

    // opt in to >48KB dynamic smem (idempotent)
    cudaFuncSetAttribute(gemm_xl, cudaFuncAttributeMaxDynamicSharedMemorySize,
                         GEMM_SMEM_BYTES);
    cudaFuncSetAttribute(gemm_qkv_xl, cudaFuncAttributeMaxDynamicSharedMemorySize,
                         GEMM_SMEM_BYTES);
    cudaFuncSetAttribute(av_v6, cudaFuncAttributeMaxDynamicSharedMemorySize,
                         AV_SMEM_BYTES);

    // 1) QKV projections (merged, 128x128 tiles)
    gemm_qkv_xl<<<dim3(8, 32, 3), 256, GEMM_SMEM_BYTES>>>(
        q, k, v, w_q, w_k, w_v, b_q, b_k, b_v, p_qh, p_kh, p_vh);

    // 2) Scores + gate/mask + exp + partial row sums (unnormalized attn)
    scores_v5<<<dim3(16, 16, ZH), 256, SC_SMEM_BYTES>>>(p_qh, p_kh, gate, mask, attn_ptr, p_part);

    // 3) AV (in-kernel invsum): MMA unnormalized P, scale ctx; terminal attn write
    av_v6<<<dim3(16, ZH), 256, AV_SMEM_BYTES>>>(attn_ptr, p_part, p_vh, p_ctx, write_attn);

    // 4) FC projection (128x128 tiles)
    gemm_xl<<<dim3(8, 32), 256, GEMM_SMEM_BYTES>>>(p_ctx, w_fc, b_fc, p_fc, DMOD, DMOD, DMOD);

    // 5) Residual + LayerNorm -> final out (warp-per-row)
    ln_warp<<<512, 256>>>(q, ln_g, ln_b, p_fc, out_ptr);
}